// round 2
// baseline (speedup 1.0000x reference)
#include <cuda_runtime.h>
#include <math.h>

#define BATCH 4
#define CIN   256
#define DD    64
#define HW    4096
#define NPIX  4096

typedef unsigned long long u64;

// scratch (no cudaMalloc allowed)
__device__ float g_att[BATCH*DD*HW];   // in-projection output
__device__ float g_q[BATCH*DD*HW];
__device__ float g_k[BATCH*DD*HW];
__device__ float g_v[BATCH*DD*HW];
__device__ float g_ao[BATCH*DD*HW];    // attention output

// packed f32x2 helpers (SASS FFMA2 — 2 fp32 FMA per issue slot)
__device__ __forceinline__ void ffma2(u64 &acc, u64 a, u64 b) {
    asm("fma.rn.f32x2 %0, %1, %2, %0;" : "+l"(acc) : "l"(a), "l"(b));
}
__device__ __forceinline__ u64 fmul2(u64 a, u64 b) {
    u64 d; asm("mul.rn.f32x2 %0, %1, %2;" : "=l"(d) : "l"(a), "l"(b)); return d;
}
__device__ __forceinline__ float lo32(u64 v) { return __uint_as_float((unsigned)v); }
__device__ __forceinline__ float hi32(u64 v) { return __uint_as_float((unsigned)(v >> 32)); }
__device__ __forceinline__ u64 pack2(float l, float h) {
    return ((u64)__float_as_uint(h) << 32) | (u64)__float_as_uint(l);
}

// ---------------------------------------------------------------------------
// 1x1 in-projection: att[b,d,p] = sum_c w[d,c] * x[b,c,p] + bias[d]
// ---------------------------------------------------------------------------
__global__ __launch_bounds__(256) void k_inproj(const float* __restrict__ x,
                                                const float* __restrict__ w,
                                                const float* __restrict__ bias) {
    int b  = blockIdx.y;
    int p0 = blockIdx.x * 64;
    int tid = threadIdx.x;
    int tp = tid & 63, tg = tid >> 6;
    __shared__ float xs[32][65];
    __shared__ float ws[64][33];
    float acc[16];
#pragma unroll
    for (int i = 0; i < 16; i++) acc[i] = 0.f;

    for (int c0 = 0; c0 < CIN; c0 += 32) {
        __syncthreads();
#pragma unroll
        for (int r = 0; r < 8; r++) {
            int lin = tid + r * 256;
            int cc = lin >> 6, pp = lin & 63;
            xs[cc][pp] = x[(size_t)(b*CIN + c0 + cc)*HW + p0 + pp];
        }
#pragma unroll
        for (int r = 0; r < 8; r++) {
            int lin = tid + r * 256;
            int dd = lin >> 5, cc = lin & 31;
            ws[dd][cc] = w[dd*CIN + c0 + cc];
        }
        __syncthreads();
#pragma unroll 8
        for (int cc = 0; cc < 32; cc++) {
            float xv = xs[cc][tp];
#pragma unroll
            for (int dd = 0; dd < 16; dd++)
                acc[dd] += ws[tg*16 + dd][cc] * xv;
        }
    }
#pragma unroll
    for (int dd = 0; dd < 16; dd++) {
        int d = tg*16 + dd;
        g_att[(size_t)(b*DD + d)*HW + p0 + tp] = acc[dd] + bias[d];
    }
}

// ---------------------------------------------------------------------------
// 3x3 conv (pad 1), D=64 -> D=64. One kernel does q/k/v via blockIdx.z.
// ---------------------------------------------------------------------------
#define ICCH 16
#define CONV_SMEM ((ICCH*324 + 64*ICCH*9) * 4)

__global__ __launch_bounds__(256) void k_conv3x3(const float* __restrict__ wq, const float* __restrict__ bq,
                                                 const float* __restrict__ wk, const float* __restrict__ bk,
                                                 const float* __restrict__ wv, const float* __restrict__ bv) {
    extern __shared__ float sm[];
    float* patch = sm;                  // [ICCH][18][18]
    float* ws    = sm + ICCH*324;       // [64][ICCH][9]

    int b     = blockIdx.z / 3;
    int which = blockIdx.z % 3;
    const float* w    = (which == 0) ? wq : (which == 1) ? wk : wv;
    const float* bias = (which == 0) ? bq : (which == 1) ? bk : bv;
    float* out        = (which == 0) ? g_q : (which == 1) ? g_k : g_v;

    int ty0 = blockIdx.y * 16, tx0 = blockIdx.x * 16;
    int tid = threadIdx.x;
    int tq = tid & 63, tg = tid >> 6;
    int qx = tq & 7, qy = tq >> 3;

    float acc[4][16];
#pragma unroll
    for (int p = 0; p < 4; p++)
#pragma unroll
        for (int o = 0; o < 16; o++) acc[p][o] = 0.f;

    for (int c0 = 0; c0 < DD; c0 += ICCH) {
        __syncthreads();
        for (int r = 0; r < 21; r++) {
            int lin = tid + r * 256;
            if (lin < ICCH*324) {
                int ic = lin / 324, rem = lin % 324;
                int py = rem / 18, px = rem % 18;
                int gy = ty0 + py - 1, gx = tx0 + px - 1;
                float v = 0.f;
                if (gy >= 0 && gy < 64 && gx >= 0 && gx < 64)
                    v = g_att[(size_t)(b*DD + c0 + ic)*HW + gy*64 + gx];
                patch[lin] = v;
            }
        }
        for (int r = 0; r < 36; r++) {
            int lin = tid + r * 256;
            int oc = lin / 144, rem = lin % 144;
            int ic = rem / 9, tap = rem % 9;
            ws[lin] = w[oc*576 + (c0 + ic)*9 + tap];
        }
        __syncthreads();

#pragma unroll 1
        for (int ic = 0; ic < ICCH; ic++) {
            float in44[4][4];
#pragma unroll
            for (int iy = 0; iy < 4; iy++)
#pragma unroll
                for (int ix = 0; ix < 4; ix++)
                    in44[iy][ix] = patch[ic*324 + (qy*2 + iy)*18 + qx*2 + ix];
#pragma unroll
            for (int o = 0; o < 16; o++) {
                const float* wp = ws + (tg*16 + o)*144 + ic*9;
                float w0 = wp[0], w1 = wp[1], w2 = wp[2];
                float w3 = wp[3], w4 = wp[4], w5 = wp[5];
                float w6 = wp[6], w7 = wp[7], w8 = wp[8];
#pragma unroll
                for (int dy = 0; dy < 2; dy++)
#pragma unroll
                    for (int dx = 0; dx < 2; dx++) {
                        acc[dy*2 + dx][o] +=
                              w0*in44[dy  ][dx] + w1*in44[dy  ][dx+1] + w2*in44[dy  ][dx+2]
                            + w3*in44[dy+1][dx] + w4*in44[dy+1][dx+1] + w5*in44[dy+1][dx+2]
                            + w6*in44[dy+2][dx] + w7*in44[dy+2][dx+1] + w8*in44[dy+2][dx+2];
                    }
            }
        }
    }
#pragma unroll
    for (int o = 0; o < 16; o++) {
        int oc = tg*16 + o;
        float bb = bias[oc];
#pragma unroll
        for (int dy = 0; dy < 2; dy++)
#pragma unroll
            for (int dx = 0; dx < 2; dx++)
                out[(size_t)(b*DD + oc)*HW + (ty0 + qy*2 + dy)*64 + tx0 + qx*2 + dx] =
                    acc[dy*2 + dx][o] + bb;
    }
}

// ---------------------------------------------------------------------------
// Flash attention, fp32 with packed f32x2 FMA (FFMA2).
// Layouts (all stride 68 floats, 16B-aligned rows):
//   Qs[i][c], Ks[j][c]  (reduction dim c contiguous -> ulonglong2 loads)
//   Vs[c][j], Ps[i][j]  (reduction dim j contiguous)
// Packed accumulators hold (even,odd) partial sums of the reduction dim;
// added together at the end -> exact fp32 math, half the issue slots.
// ---------------------------------------------------------------------------
#define ATTN_SMEM (4 * 64 * 68 * 4)

__global__ __launch_bounds__(256, 2) void k_attn() {
    extern __shared__ float sm[];
    float* Qs = sm;             // [i][c]
    float* Ks = sm + 64*68;     // [j][c]
    float* Vs = sm + 2*64*68;   // [c][j]
    float* Ps = sm + 3*64*68;   // [i][j]

    int b  = blockIdx.y;
    int i0 = blockIdx.x * 64;
    int tid = threadIdx.x;
    int tj = tid & 15, ti = tid >> 4;
    int ti4 = ti * 4, tj4 = tj * 4;

    const float* Qg = g_q + (size_t)b*DD*NPIX;
    const float* Kg = g_k + (size_t)b*DD*NPIX;
    const float* Vg = g_v + (size_t)b*DD*NPIX;

    // load Q transposed: Qs[i][c]
#pragma unroll
    for (int r = 0; r < 16; r++) {
        int lin = tid + r * 256;
        int c = lin >> 6, ii = lin & 63;
        Qs[ii*68 + c] = Qg[(size_t)c*NPIX + i0 + ii];
    }

    float m[4], l[4];
    u64 O2[4][4];
#pragma unroll
    for (int ii = 0; ii < 4; ii++) {
        m[ii] = -1e30f; l[ii] = 0.f;
#pragma unroll
        for (int cc = 0; cc < 4; cc++) O2[ii][cc] = 0ull;
    }

    for (int j0 = 0; j0 < NPIX; j0 += 64) {
        __syncthreads();
#pragma unroll
        for (int r = 0; r < 16; r++) {
            int lin = tid + r * 256;
            int c = lin >> 6, jj = lin & 63;
            Ks[jj*68 + c] = Kg[(size_t)c*NPIX + j0 + jj];  // transposed
            Vs[c*68 + jj] = Vg[(size_t)c*NPIX + j0 + jj];  // natural
        }
        __syncthreads();

        // S = Q^T K : packed over c pairs
        u64 s2[4][4];
#pragma unroll
        for (int ii = 0; ii < 4; ii++)
#pragma unroll
            for (int jj = 0; jj < 4; jj++) s2[ii][jj] = 0ull;
#pragma unroll 8
        for (int c = 0; c < 64; c += 4) {
            ulonglong2 q[4], k[4];
#pragma unroll
            for (int ii = 0; ii < 4; ii++) q[ii] = *(const ulonglong2*)&Qs[(ti4+ii)*68 + c];
#pragma unroll
            for (int jj = 0; jj < 4; jj++) k[jj] = *(const ulonglong2*)&Ks[(tj4+jj)*68 + c];
#pragma unroll
            for (int ii = 0; ii < 4; ii++)
#pragma unroll
                for (int jj = 0; jj < 4; jj++) {
                    ffma2(s2[ii][jj], q[ii].x, k[jj].x);
                    ffma2(s2[ii][jj], q[ii].y, k[jj].y);
                }
        }

        // online softmax per row (16-lane row groups)
        float p[4][4];
#pragma unroll
        for (int ii = 0; ii < 4; ii++) {
            float s0 = lo32(s2[ii][0]) + hi32(s2[ii][0]);
            float s1 = lo32(s2[ii][1]) + hi32(s2[ii][1]);
            float s2v = lo32(s2[ii][2]) + hi32(s2[ii][2]);
            float s3 = lo32(s2[ii][3]) + hi32(s2[ii][3]);
            float rm = fmaxf(fmaxf(s0, s1), fmaxf(s2v, s3));
            rm = fmaxf(rm, __shfl_xor_sync(0xffffffffu, rm, 1));
            rm = fmaxf(rm, __shfl_xor_sync(0xffffffffu, rm, 2));
            rm = fmaxf(rm, __shfl_xor_sync(0xffffffffu, rm, 4));
            rm = fmaxf(rm, __shfl_xor_sync(0xffffffffu, rm, 8));
            float mn = fmaxf(m[ii], rm);
            float sc = __expf(m[ii] - mn);
            m[ii] = mn;
            p[ii][0] = __expf(s0 - mn);
            p[ii][1] = __expf(s1 - mn);
            p[ii][2] = __expf(s2v - mn);
            p[ii][3] = __expf(s3 - mn);
            float rs = p[ii][0] + p[ii][1] + p[ii][2] + p[ii][3];
            rs += __shfl_xor_sync(0xffffffffu, rs, 1);
            rs += __shfl_xor_sync(0xffffffffu, rs, 2);
            rs += __shfl_xor_sync(0xffffffffu, rs, 4);
            rs += __shfl_xor_sync(0xffffffffu, rs, 8);
            l[ii] = l[ii]*sc + rs;
            u64 sc2 = pack2(sc, sc);
#pragma unroll
            for (int cc = 0; cc < 4; cc++) O2[ii][cc] = fmul2(O2[ii][cc], sc2);
        }

#pragma unroll
        for (int ii = 0; ii < 4; ii++)
            *(float4*)&Ps[(ti4 + ii)*68 + tj4] = make_float4(p[ii][0], p[ii][1], p[ii][2], p[ii][3]);
        __syncthreads();

        // O[i][c] += sum_j P[i][j] V[c][j] : packed over j pairs
#pragma unroll 8
        for (int j = 0; j < 64; j += 4) {
            ulonglong2 pr[4], vr[4];
#pragma unroll
            for (int ii = 0; ii < 4; ii++) pr[ii] = *(const ulonglong2*)&Ps[(ti4+ii)*68 + j];
#pragma unroll
            for (int cc = 0; cc < 4; cc++) vr[cc] = *(const ulonglong2*)&Vs[(tj4+cc)*68 + j];
#pragma unroll
            for (int ii = 0; ii < 4; ii++)
#pragma unroll
                for (int cc = 0; cc < 4; cc++) {
                    ffma2(O2[ii][cc], pr[ii].x, vr[cc].x);
                    ffma2(O2[ii][cc], pr[ii].y, vr[cc].y);
                }
        }
    }

    __syncthreads();
    // stage normalized output (c-major) into Ks, then write coalesced
#pragma unroll
    for (int ii = 0; ii < 4; ii++) {
        float inv = 1.f / l[ii];
#pragma unroll
        for (int cc = 0; cc < 4; cc++)
            Ks[(tj4 + cc)*68 + ti4 + ii] = (lo32(O2[ii][cc]) + hi32(O2[ii][cc])) * inv;
    }
    __syncthreads();
#pragma unroll
    for (int r = 0; r < 16; r++) {
        int lin = tid + r * 256;
        int c = lin >> 6, ii = lin & 63;
        g_ao[(size_t)(b*DD + c)*NPIX + i0 + ii] = Ks[c*68 + ii];
    }
}

// ---------------------------------------------------------------------------
// out-projection (64->256) + residual gamma*x + channel LayerNorm, fused.
// ---------------------------------------------------------------------------
__global__ __launch_bounds__(256) void k_outproj_ln(const float* __restrict__ x,
                                                    const float* __restrict__ w,
                                                    const float* __restrict__ bias,
                                                    const float* __restrict__ gamma,
                                                    const float* __restrict__ lnw,
                                                    const float* __restrict__ lnb,
                                                    float* __restrict__ out) {
    int b  = blockIdx.y;
    int p0 = blockIdx.x * 64;
    int tid = threadIdx.x;
    int tp = tid & 63, tg = tid >> 6;
    __shared__ float xs[16][65];
    __shared__ float ws[256][17];
    __shared__ float red[2][4][64];

    float acc[64];
#pragma unroll
    for (int i = 0; i < 64; i++) acc[i] = 0.f;

    for (int d0 = 0; d0 < DD; d0 += 16) {
        __syncthreads();
#pragma unroll
        for (int r = 0; r < 4; r++) {
            int lin = tid + r * 256;
            int cc = lin >> 6, pp = lin & 63;
            xs[cc][pp] = g_ao[(size_t)(b*DD + d0 + cc)*HW + p0 + pp];
        }
#pragma unroll
        for (int r = 0; r < 16; r++) {
            int lin = tid + r * 256;
            int co = lin >> 4, cc = lin & 15;
            ws[co][cc] = w[co*DD + d0 + cc];
        }
        __syncthreads();
#pragma unroll 4
        for (int cc = 0; cc < 16; cc++) {
            float xv = xs[cc][tp];
#pragma unroll
            for (int oo = 0; oo < 64; oo++)
                acc[oo] += ws[tg*64 + oo][cc] * xv;
        }
    }

    float g = gamma[0];
    float s = 0.f, ss = 0.f;
#pragma unroll
    for (int oo = 0; oo < 64; oo++) {
        int co = tg*64 + oo;
        float v = g * x[(size_t)(b*CIN + co)*HW + p0 + tp] + acc[oo] + bias[co];
        acc[oo] = v;
        s += v; ss += v*v;
    }
    red[0][tg][tp] = s;
    red[1][tg][tp] = ss;
    __syncthreads();
    float st  = red[0][0][tp] + red[0][1][tp] + red[0][2][tp] + red[0][3][tp];
    float sst = red[1][0][tp] + red[1][1][tp] + red[1][2][tp] + red[1][3][tp];
    float mu  = st * (1.f/256.f);
    float var = sst * (1.f/256.f) - mu*mu;
    float rstd = rsqrtf(var + 1e-5f);
#pragma unroll
    for (int oo = 0; oo < 64; oo++) {
        int co = tg*64 + oo;
        out[(size_t)(b*CIN + co)*HW + p0 + tp] = (acc[oo] - mu) * rstd * lnw[co] + lnb[co];
    }
}

// ---------------------------------------------------------------------------
extern "C" void kernel_launch(void* const* d_in, const int* in_sizes, int n_in,
                              void* d_out, int out_size) {
    const float* x     = (const float*)d_in[0];
    const float* w_in  = (const float*)d_in[1];
    const float* b_in  = (const float*)d_in[2];
    const float* wq    = (const float*)d_in[3];
    const float* bq    = (const float*)d_in[4];
    const float* wk    = (const float*)d_in[5];
    const float* bk    = (const float*)d_in[6];
    const float* wv    = (const float*)d_in[7];
    const float* bv    = (const float*)d_in[8];
    const float* w_out = (const float*)d_in[9];
    const float* b_out = (const float*)d_in[10];
    const float* gamma = (const float*)d_in[11];
    const float* ln_w  = (const float*)d_in[12];
    const float* ln_b  = (const float*)d_in[13];
    float* out = (float*)d_out;

    cudaFuncSetAttribute(k_conv3x3, cudaFuncAttributeMaxDynamicSharedMemorySize, CONV_SMEM);
    cudaFuncSetAttribute(k_attn,    cudaFuncAttributeMaxDynamicSharedMemorySize, ATTN_SMEM);

    k_inproj<<<dim3(64, BATCH), 256>>>(x, w_in, b_in);
    k_conv3x3<<<dim3(4, 4, BATCH*3), 256, CONV_SMEM>>>(wq, bq, wk, bk, wv, bv);
    k_attn<<<dim3(64, BATCH), 256, ATTN_SMEM>>>();
    k_outproj_ln<<<dim3(64, BATCH), 256>>>(x, w_out, b_out, gamma, ln_w, ln_b, out);
}

// round 3
// speedup vs baseline: 1.2575x; 1.2575x over previous
#include <cuda_runtime.h>
#include <math.h>

#define BATCH 4
#define CIN   256
#define DD    64
#define HW    4096
#define NPIX  4096

typedef unsigned long long u64;

// scratch (no cudaMalloc allowed)
__device__ float g_att[BATCH*DD*HW];   // in-projection output
__device__ float g_q[BATCH*DD*HW];
__device__ float g_k[BATCH*DD*HW];
__device__ float g_v[BATCH*DD*HW];
__device__ float g_ao[BATCH*DD*HW];    // attention output

// packed f32x2 helpers (SASS FFMA2 — 2 fp32 FMA per issue slot)
__device__ __forceinline__ void ffma2(u64 &acc, u64 a, u64 b) {
    asm("fma.rn.f32x2 %0, %1, %2, %0;" : "+l"(acc) : "l"(a), "l"(b));
}
__device__ __forceinline__ u64 fmul2(u64 a, u64 b) {
    u64 d; asm("mul.rn.f32x2 %0, %1, %2;" : "=l"(d) : "l"(a), "l"(b)); return d;
}
__device__ __forceinline__ float lo32(u64 v) { return __uint_as_float((unsigned)v); }
__device__ __forceinline__ float hi32(u64 v) { return __uint_as_float((unsigned)(v >> 32)); }
__device__ __forceinline__ u64 pack2(float l, float h) {
    u64 d; asm("mov.b64 %0, {%1, %2};" : "=l"(d) : "f"(l), "f"(h)); return d;
}

// ---------------------------------------------------------------------------
// 1x1 in-projection: att[b,d,p] = sum_c w[d,c] * x[b,c,p] + bias[d]
// ---------------------------------------------------------------------------
__global__ __launch_bounds__(256) void k_inproj(const float* __restrict__ x,
                                                const float* __restrict__ w,
                                                const float* __restrict__ bias) {
    int b  = blockIdx.y;
    int p0 = blockIdx.x * 64;
    int tid = threadIdx.x;
    int tp = tid & 63, tg = tid >> 6;
    __shared__ float xs[32][65];
    __shared__ float ws[64][33];
    float acc[16];
#pragma unroll
    for (int i = 0; i < 16; i++) acc[i] = 0.f;

    for (int c0 = 0; c0 < CIN; c0 += 32) {
        __syncthreads();
#pragma unroll
        for (int r = 0; r < 8; r++) {
            int lin = tid + r * 256;
            int cc = lin >> 6, pp = lin & 63;
            xs[cc][pp] = x[(size_t)(b*CIN + c0 + cc)*HW + p0 + pp];
        }
#pragma unroll
        for (int r = 0; r < 8; r++) {
            int lin = tid + r * 256;
            int dd = lin >> 5, cc = lin & 31;
            ws[dd][cc] = w[dd*CIN + c0 + cc];
        }
        __syncthreads();
#pragma unroll 8
        for (int cc = 0; cc < 32; cc++) {
            float xv = xs[cc][tp];
#pragma unroll
            for (int dd = 0; dd < 16; dd++)
                acc[dd] += ws[tg*16 + dd][cc] * xv;
        }
    }
#pragma unroll
    for (int dd = 0; dd < 16; dd++) {
        int d = tg*16 + dd;
        g_att[(size_t)(b*DD + d)*HW + p0 + tp] = acc[dd] + bias[d];
    }
}

// ---------------------------------------------------------------------------
// 3x3 conv (pad 1), D=64 -> D=64. One kernel does q/k/v via blockIdx.z.
// ---------------------------------------------------------------------------
#define ICCH 16
#define CONV_SMEM ((ICCH*324 + 64*ICCH*9) * 4)

__global__ __launch_bounds__(256) void k_conv3x3(const float* __restrict__ wq, const float* __restrict__ bq,
                                                 const float* __restrict__ wk, const float* __restrict__ bk,
                                                 const float* __restrict__ wv, const float* __restrict__ bv) {
    extern __shared__ float sm[];
    float* patch = sm;                  // [ICCH][18][18]
    float* ws    = sm + ICCH*324;       // [64][ICCH][9]

    int b     = blockIdx.z / 3;
    int which = blockIdx.z % 3;
    const float* w    = (which == 0) ? wq : (which == 1) ? wk : wv;
    const float* bias = (which == 0) ? bq : (which == 1) ? bk : bv;
    float* out        = (which == 0) ? g_q : (which == 1) ? g_k : g_v;

    int ty0 = blockIdx.y * 16, tx0 = blockIdx.x * 16;
    int tid = threadIdx.x;
    int tq = tid & 63, tg = tid >> 6;
    int qx = tq & 7, qy = tq >> 3;

    float acc[4][16];
#pragma unroll
    for (int p = 0; p < 4; p++)
#pragma unroll
        for (int o = 0; o < 16; o++) acc[p][o] = 0.f;

    for (int c0 = 0; c0 < DD; c0 += ICCH) {
        __syncthreads();
        for (int r = 0; r < 21; r++) {
            int lin = tid + r * 256;
            if (lin < ICCH*324) {
                int ic = lin / 324, rem = lin % 324;
                int py = rem / 18, px = rem % 18;
                int gy = ty0 + py - 1, gx = tx0 + px - 1;
                float v = 0.f;
                if (gy >= 0 && gy < 64 && gx >= 0 && gx < 64)
                    v = g_att[(size_t)(b*DD + c0 + ic)*HW + gy*64 + gx];
                patch[lin] = v;
            }
        }
        for (int r = 0; r < 36; r++) {
            int lin = tid + r * 256;
            int oc = lin / 144, rem = lin % 144;
            int ic = rem / 9, tap = rem % 9;
            ws[lin] = w[oc*576 + (c0 + ic)*9 + tap];
        }
        __syncthreads();

#pragma unroll 1
        for (int ic = 0; ic < ICCH; ic++) {
            float in44[4][4];
#pragma unroll
            for (int iy = 0; iy < 4; iy++)
#pragma unroll
                for (int ix = 0; ix < 4; ix++)
                    in44[iy][ix] = patch[ic*324 + (qy*2 + iy)*18 + qx*2 + ix];
#pragma unroll
            for (int o = 0; o < 16; o++) {
                const float* wp = ws + (tg*16 + o)*144 + ic*9;
                float w0 = wp[0], w1 = wp[1], w2 = wp[2];
                float w3 = wp[3], w4 = wp[4], w5 = wp[5];
                float w6 = wp[6], w7 = wp[7], w8 = wp[8];
#pragma unroll
                for (int dy = 0; dy < 2; dy++)
#pragma unroll
                    for (int dx = 0; dx < 2; dx++) {
                        acc[dy*2 + dx][o] +=
                              w0*in44[dy  ][dx] + w1*in44[dy  ][dx+1] + w2*in44[dy  ][dx+2]
                            + w3*in44[dy+1][dx] + w4*in44[dy+1][dx+1] + w5*in44[dy+1][dx+2]
                            + w6*in44[dy+2][dx] + w7*in44[dy+2][dx+1] + w8*in44[dy+2][dx+2];
                    }
            }
        }
    }
#pragma unroll
    for (int o = 0; o < 16; o++) {
        int oc = tg*16 + o;
        float bb = bias[oc];
#pragma unroll
        for (int dy = 0; dy < 2; dy++)
#pragma unroll
            for (int dx = 0; dx < 2; dx++)
                out[(size_t)(b*DD + oc)*HW + (ty0 + qy*2 + dy)*64 + tx0 + qx*2 + dx] =
                    acc[dy*2 + dx][o] + bb;
    }
}

// ---------------------------------------------------------------------------
// Flash attention, fp32, FFMA2 with duplicated-operand SMEM layouts.
// Layouts (conflict-free: reduction dim is the ROW index, all lanes of an
// instruction read within one row):
//   Qs[c][i]   stride 68  (i contiguous -> natural q-pairs along i)
//   Kd[c][2j]  stride 132 (each k stored twice -> (k,k) dup pairs)
//   Vs[j][c]   stride 68  (c contiguous -> natural v-pairs along c)
//   Pd[i][2j]  stride 132 (each p stored twice -> (p,p) dup pairs)
// S accumulators pack (S[i0][j], S[i1][j]); O accumulators pack
// (O[i][c0], O[i][c1]). FLOP order identical to the scalar version.
// ---------------------------------------------------------------------------
#define ATTN_SMEM ((2*64*68 + 2*64*132) * 4)

__global__ __launch_bounds__(256) void k_attn() {
    extern __shared__ float sm[];
    float* Qs = sm;                       // [c][i]  stride 68
    float* Vs = sm + 64*68;               // [j][c]  stride 68
    float* Kd = sm + 2*64*68;             // [c][2j] stride 132
    float* Pd = sm + 2*64*68 + 64*132;    // [i][2j] stride 132

    int b  = blockIdx.y;
    int i0 = blockIdx.x * 64;
    int tid = threadIdx.x;
    int tj = tid & 15, ti = tid >> 4;
    int ti4 = ti * 4, tj4 = tj * 4;

    const float* Qg = g_q + (size_t)b*DD*NPIX;
    const float* Kg = g_k + (size_t)b*DD*NPIX;
    const float* Vg = g_v + (size_t)b*DD*NPIX;

#pragma unroll
    for (int r = 0; r < 16; r++) {
        int lin = tid + r * 256;
        int c = lin >> 6, ii = lin & 63;
        Qs[c*68 + ii] = Qg[(size_t)c*NPIX + i0 + ii];
    }

    float m[4], l[4];
    u64 O2[4][2];              // [ii][cpair] -> (O[i][c0],O[i][c1]) etc.
#pragma unroll
    for (int ii = 0; ii < 4; ii++) {
        m[ii] = -1e30f; l[ii] = 0.f;
        O2[ii][0] = 0ull; O2[ii][1] = 0ull;
    }

    for (int j0 = 0; j0 < NPIX; j0 += 64) {
        __syncthreads();
#pragma unroll
        for (int r = 0; r < 16; r++) {
            int lin = tid + r * 256;
            int c = lin >> 6, jj = lin & 63;
            float kv = Kg[(size_t)c*NPIX + j0 + jj];
            float vv = Vg[(size_t)c*NPIX + j0 + jj];
            Kd[c*132 + 2*jj]     = kv;
            Kd[c*132 + 2*jj + 1] = kv;
            Vs[jj*68 + c] = vv;
        }
        __syncthreads();

        // S = Q^T K : s2[ip][j] = (S[i_{2ip}][j], S[i_{2ip+1}][j])
        u64 s2[2][4];
#pragma unroll
        for (int ip = 0; ip < 2; ip++)
#pragma unroll
            for (int jj = 0; jj < 4; jj++) s2[ip][jj] = 0ull;
#pragma unroll 4
        for (int c = 0; c < 64; c++) {
            ulonglong2 qa = *(const ulonglong2*)&Qs[c*68 + ti4];       // (i0,i1),(i2,i3)
            ulonglong2 k0 = *(const ulonglong2*)&Kd[c*132 + 2*tj4];    // (j0,j0),(j1,j1)
            ulonglong2 k1 = *(const ulonglong2*)&Kd[c*132 + 2*tj4+4];  // (j2,j2),(j3,j3)
            ffma2(s2[0][0], qa.x, k0.x); ffma2(s2[0][1], qa.x, k0.y);
            ffma2(s2[0][2], qa.x, k1.x); ffma2(s2[0][3], qa.x, k1.y);
            ffma2(s2[1][0], qa.y, k0.x); ffma2(s2[1][1], qa.y, k0.y);
            ffma2(s2[1][2], qa.y, k1.x); ffma2(s2[1][3], qa.y, k1.y);
        }

        // online softmax per row (16-lane row groups)
        float p[4][4];
#pragma unroll
        for (int ii = 0; ii < 4; ii++) {
            int ip = ii >> 1;
            float s0, s1, s2v, s3;
            if ((ii & 1) == 0) {
                s0 = lo32(s2[ip][0]); s1 = lo32(s2[ip][1]);
                s2v = lo32(s2[ip][2]); s3 = lo32(s2[ip][3]);
            } else {
                s0 = hi32(s2[ip][0]); s1 = hi32(s2[ip][1]);
                s2v = hi32(s2[ip][2]); s3 = hi32(s2[ip][3]);
            }
            float rm = fmaxf(fmaxf(s0, s1), fmaxf(s2v, s3));
            rm = fmaxf(rm, __shfl_xor_sync(0xffffffffu, rm, 1));
            rm = fmaxf(rm, __shfl_xor_sync(0xffffffffu, rm, 2));
            rm = fmaxf(rm, __shfl_xor_sync(0xffffffffu, rm, 4));
            rm = fmaxf(rm, __shfl_xor_sync(0xffffffffu, rm, 8));
            float mn = fmaxf(m[ii], rm);
            float sc = __expf(m[ii] - mn);
            m[ii] = mn;
            p[ii][0] = __expf(s0 - mn);
            p[ii][1] = __expf(s1 - mn);
            p[ii][2] = __expf(s2v - mn);
            p[ii][3] = __expf(s3 - mn);
            float rs = p[ii][0] + p[ii][1] + p[ii][2] + p[ii][3];
            rs += __shfl_xor_sync(0xffffffffu, rs, 1);
            rs += __shfl_xor_sync(0xffffffffu, rs, 2);
            rs += __shfl_xor_sync(0xffffffffu, rs, 4);
            rs += __shfl_xor_sync(0xffffffffu, rs, 8);
            l[ii] = l[ii]*sc + rs;
            u64 sc2 = pack2(sc, sc);
            O2[ii][0] = fmul2(O2[ii][0], sc2);
            O2[ii][1] = fmul2(O2[ii][1], sc2);
        }

        // write P duplicated: Pd[i][2j], (p,p) pairs
#pragma unroll
        for (int ii = 0; ii < 4; ii++) {
            *(float4*)&Pd[(ti4 + ii)*132 + 2*tj4]     = make_float4(p[ii][0], p[ii][0], p[ii][1], p[ii][1]);
            *(float4*)&Pd[(ti4 + ii)*132 + 2*tj4 + 4] = make_float4(p[ii][2], p[ii][2], p[ii][3], p[ii][3]);
        }
        __syncthreads();

        // O[i][c] += sum_j P[i][j] V[j][c]
#pragma unroll 4
        for (int j = 0; j < 64; j += 2) {
            ulonglong2 va = *(const ulonglong2*)&Vs[j*68 + tj4];       // j  : (c0,c1),(c2,c3)
            ulonglong2 vb = *(const ulonglong2*)&Vs[(j+1)*68 + tj4];   // j+1
            ulonglong2 pd0 = *(const ulonglong2*)&Pd[(ti4+0)*132 + 2*j];
            ulonglong2 pd1 = *(const ulonglong2*)&Pd[(ti4+1)*132 + 2*j];
            ulonglong2 pd2 = *(const ulonglong2*)&Pd[(ti4+2)*132 + 2*j];
            ulonglong2 pd3 = *(const ulonglong2*)&Pd[(ti4+3)*132 + 2*j];
            ffma2(O2[0][0], pd0.x, va.x); ffma2(O2[0][1], pd0.x, va.y);
            ffma2(O2[1][0], pd1.x, va.x); ffma2(O2[1][1], pd1.x, va.y);
            ffma2(O2[2][0], pd2.x, va.x); ffma2(O2[2][1], pd2.x, va.y);
            ffma2(O2[3][0], pd3.x, va.x); ffma2(O2[3][1], pd3.x, va.y);
            ffma2(O2[0][0], pd0.y, vb.x); ffma2(O2[0][1], pd0.y, vb.y);
            ffma2(O2[1][0], pd1.y, vb.x); ffma2(O2[1][1], pd1.y, vb.y);
            ffma2(O2[2][0], pd2.y, vb.x); ffma2(O2[2][1], pd2.y, vb.y);
            ffma2(O2[3][0], pd3.y, vb.x); ffma2(O2[3][1], pd3.y, vb.y);
        }
    }

    __syncthreads();
    // stage normalized output into Qs as [c][i], then write coalesced
#pragma unroll
    for (int ii = 0; ii < 4; ii++) {
        float inv = 1.f / l[ii];
        float o0 = lo32(O2[ii][0]) * inv;
        float o1 = hi32(O2[ii][0]) * inv;
        float o2 = lo32(O2[ii][1]) * inv;
        float o3 = hi32(O2[ii][1]) * inv;
        Qs[(tj4 + 0)*68 + ti4 + ii] = o0;
        Qs[(tj4 + 1)*68 + ti4 + ii] = o1;
        Qs[(tj4 + 2)*68 + ti4 + ii] = o2;
        Qs[(tj4 + 3)*68 + ti4 + ii] = o3;
    }
    __syncthreads();
#pragma unroll
    for (int r = 0; r < 16; r++) {
        int lin = tid + r * 256;
        int c = lin >> 6, ii = lin & 63;
        g_ao[(size_t)(b*DD + c)*NPIX + i0 + ii] = Qs[c*68 + ii];
    }
}

// ---------------------------------------------------------------------------
// out-projection (64->256) + residual gamma*x + channel LayerNorm, fused.
// ---------------------------------------------------------------------------
__global__ __launch_bounds__(256) void k_outproj_ln(const float* __restrict__ x,
                                                    const float* __restrict__ w,
                                                    const float* __restrict__ bias,
                                                    const float* __restrict__ gamma,
                                                    const float* __restrict__ lnw,
                                                    const float* __restrict__ lnb,
                                                    float* __restrict__ out) {
    int b  = blockIdx.y;
    int p0 = blockIdx.x * 64;
    int tid = threadIdx.x;
    int tp = tid & 63, tg = tid >> 6;
    __shared__ float xs[16][65];
    __shared__ float ws[256][17];
    __shared__ float red[2][4][64];

    float acc[64];
#pragma unroll
    for (int i = 0; i < 64; i++) acc[i] = 0.f;

    for (int d0 = 0; d0 < DD; d0 += 16) {
        __syncthreads();
#pragma unroll
        for (int r = 0; r < 4; r++) {
            int lin = tid + r * 256;
            int cc = lin >> 6, pp = lin & 63;
            xs[cc][pp] = g_ao[(size_t)(b*DD + d0 + cc)*HW + p0 + pp];
        }
#pragma unroll
        for (int r = 0; r < 16; r++) {
            int lin = tid + r * 256;
            int co = lin >> 4, cc = lin & 15;
            ws[co][cc] = w[co*DD + d0 + cc];
        }
        __syncthreads();
#pragma unroll 4
        for (int cc = 0; cc < 16; cc++) {
            float xv = xs[cc][tp];
#pragma unroll
            for (int oo = 0; oo < 64; oo++)
                acc[oo] += ws[tg*64 + oo][cc] * xv;
        }
    }

    float g = gamma[0];
    float s = 0.f, ss = 0.f;
#pragma unroll
    for (int oo = 0; oo < 64; oo++) {
        int co = tg*64 + oo;
        float v = g * x[(size_t)(b*CIN + co)*HW + p0 + tp] + acc[oo] + bias[co];
        acc[oo] = v;
        s += v; ss += v*v;
    }
    red[0][tg][tp] = s;
    red[1][tg][tp] = ss;
    __syncthreads();
    float st  = red[0][0][tp] + red[0][1][tp] + red[0][2][tp] + red[0][3][tp];
    float sst = red[1][0][tp] + red[1][1][tp] + red[1][2][tp] + red[1][3][tp];
    float mu  = st * (1.f/256.f);
    float var = sst * (1.f/256.f) - mu*mu;
    float rstd = rsqrtf(var + 1e-5f);
#pragma unroll
    for (int oo = 0; oo < 64; oo++) {
        int co = tg*64 + oo;
        out[(size_t)(b*CIN + co)*HW + p0 + tp] = (acc[oo] - mu) * rstd * lnw[co] + lnb[co];
    }
}

// ---------------------------------------------------------------------------
extern "C" void kernel_launch(void* const* d_in, const int* in_sizes, int n_in,
                              void* d_out, int out_size) {
    const float* x     = (const float*)d_in[0];
    const float* w_in  = (const float*)d_in[1];
    const float* b_in  = (const float*)d_in[2];
    const float* wq    = (const float*)d_in[3];
    const float* bq    = (const float*)d_in[4];
    const float* wk    = (const float*)d_in[5];
    const float* bk    = (const float*)d_in[6];
    const float* wv    = (const float*)d_in[7];
    const float* bv    = (const float*)d_in[8];
    const float* w_out = (const float*)d_in[9];
    const float* b_out = (const float*)d_in[10];
    const float* gamma = (const float*)d_in[11];
    const float* ln_w  = (const float*)d_in[12];
    const float* ln_b  = (const float*)d_in[13];
    float* out = (float*)d_out;

    cudaFuncSetAttribute(k_conv3x3, cudaFuncAttributeMaxDynamicSharedMemorySize, CONV_SMEM);
    cudaFuncSetAttribute(k_attn,    cudaFuncAttributeMaxDynamicSharedMemorySize, ATTN_SMEM);

    k_inproj<<<dim3(64, BATCH), 256>>>(x, w_in, b_in);
    k_conv3x3<<<dim3(4, 4, BATCH*3), 256, CONV_SMEM>>>(wq, bq, wk, bk, wv, bv);
    k_attn<<<dim3(64, BATCH), 256, ATTN_SMEM>>>();
    k_outproj_ln<<<dim3(64, BATCH), 256>>>(x, w_out, b_out, gamma, ln_w, ln_b, out);
}

// round 4
// speedup vs baseline: 3.1138x; 2.4761x over previous
#include <cuda_runtime.h>
#include <cuda_bf16.h>
#include <math.h>

#define BATCH 4
#define CIN   256
#define DD    64
#define HW    4096
#define NPIX  4096

// scratch (no cudaMalloc allowed)
__device__ float g_att[BATCH*DD*HW];   // in-projection output
__device__ float g_q[BATCH*DD*HW];
__device__ float g_k[BATCH*DD*HW];
__device__ float g_v[BATCH*DD*HW];
__device__ float g_ao[BATCH*DD*HW];    // attention output

// ---------------------------------------------------------------------------
// mma / ldmatrix helpers
// ---------------------------------------------------------------------------
__device__ __forceinline__ void ldsm_x4(unsigned* r, const void* p) {
    unsigned a = (unsigned)__cvta_generic_to_shared(p);
    asm volatile("ldmatrix.sync.aligned.m8n8.x4.shared.b16 {%0,%1,%2,%3}, [%4];"
        : "=r"(r[0]), "=r"(r[1]), "=r"(r[2]), "=r"(r[3]) : "r"(a));
}
__device__ __forceinline__ void ldsm_x4_t(unsigned* r, const void* p) {
    unsigned a = (unsigned)__cvta_generic_to_shared(p);
    asm volatile("ldmatrix.sync.aligned.m8n8.x4.trans.shared.b16 {%0,%1,%2,%3}, [%4];"
        : "=r"(r[0]), "=r"(r[1]), "=r"(r[2]), "=r"(r[3]) : "r"(a));
}
__device__ __forceinline__ void mma_bf16(float* c, const unsigned* a, const unsigned* b) {
    asm volatile("mma.sync.aligned.m16n8k16.row.col.f32.bf16.bf16.f32 "
        "{%0,%1,%2,%3}, {%4,%5,%6,%7}, {%8,%9}, {%0,%1,%2,%3};"
        : "+f"(c[0]), "+f"(c[1]), "+f"(c[2]), "+f"(c[3])
        : "r"(a[0]), "r"(a[1]), "r"(a[2]), "r"(a[3]), "r"(b[0]), "r"(b[1]));
}

// ---------------------------------------------------------------------------
// 1x1 in-projection (round-0 proven)
// ---------------------------------------------------------------------------
__global__ __launch_bounds__(256) void k_inproj(const float* __restrict__ x,
                                                const float* __restrict__ w,
                                                const float* __restrict__ bias) {
    int b  = blockIdx.y;
    int p0 = blockIdx.x * 64;
    int tid = threadIdx.x;
    int tp = tid & 63, tg = tid >> 6;
    __shared__ float xs[32][65];
    __shared__ float ws[64][33];
    float acc[16];
#pragma unroll
    for (int i = 0; i < 16; i++) acc[i] = 0.f;

    for (int c0 = 0; c0 < CIN; c0 += 32) {
        __syncthreads();
#pragma unroll
        for (int r = 0; r < 8; r++) {
            int lin = tid + r * 256;
            int cc = lin >> 6, pp = lin & 63;
            xs[cc][pp] = x[(size_t)(b*CIN + c0 + cc)*HW + p0 + pp];
        }
#pragma unroll
        for (int r = 0; r < 8; r++) {
            int lin = tid + r * 256;
            int dd = lin >> 5, cc = lin & 31;
            ws[dd][cc] = w[dd*CIN + c0 + cc];
        }
        __syncthreads();
#pragma unroll 8
        for (int cc = 0; cc < 32; cc++) {
            float xv = xs[cc][tp];
#pragma unroll
            for (int dd = 0; dd < 16; dd++)
                acc[dd] += ws[tg*16 + dd][cc] * xv;
        }
    }
#pragma unroll
    for (int dd = 0; dd < 16; dd++) {
        int d = tg*16 + dd;
        g_att[(size_t)(b*DD + d)*HW + p0 + tp] = acc[dd] + bias[d];
    }
}

// ---------------------------------------------------------------------------
// 3x3 conv (round-0 proven)
// ---------------------------------------------------------------------------
#define ICCH 16
#define CONV_SMEM ((ICCH*324 + 64*ICCH*9) * 4)

__global__ __launch_bounds__(256) void k_conv3x3(const float* __restrict__ wq, const float* __restrict__ bq,
                                                 const float* __restrict__ wk, const float* __restrict__ bk,
                                                 const float* __restrict__ wv, const float* __restrict__ bv) {
    extern __shared__ float sm[];
    float* patch = sm;                  // [ICCH][18][18]
    float* ws    = sm + ICCH*324;       // [64][ICCH][9]

    int b     = blockIdx.z / 3;
    int which = blockIdx.z % 3;
    const float* w    = (which == 0) ? wq : (which == 1) ? wk : wv;
    const float* bias = (which == 0) ? bq : (which == 1) ? bk : bv;
    float* out        = (which == 0) ? g_q : (which == 1) ? g_k : g_v;

    int ty0 = blockIdx.y * 16, tx0 = blockIdx.x * 16;
    int tid = threadIdx.x;
    int tq = tid & 63, tg = tid >> 6;
    int qx = tq & 7, qy = tq >> 3;

    float acc[4][16];
#pragma unroll
    for (int p = 0; p < 4; p++)
#pragma unroll
        for (int o = 0; o < 16; o++) acc[p][o] = 0.f;

    for (int c0 = 0; c0 < DD; c0 += ICCH) {
        __syncthreads();
        for (int r = 0; r < 21; r++) {
            int lin = tid + r * 256;
            if (lin < ICCH*324) {
                int ic = lin / 324, rem = lin % 324;
                int py = rem / 18, px = rem % 18;
                int gy = ty0 + py - 1, gx = tx0 + px - 1;
                float v = 0.f;
                if (gy >= 0 && gy < 64 && gx >= 0 && gx < 64)
                    v = g_att[(size_t)(b*DD + c0 + ic)*HW + gy*64 + gx];
                patch[lin] = v;
            }
        }
        for (int r = 0; r < 36; r++) {
            int lin = tid + r * 256;
            int oc = lin / 144, rem = lin % 144;
            int ic = rem / 9, tap = rem % 9;
            ws[lin] = w[oc*576 + (c0 + ic)*9 + tap];
        }
        __syncthreads();

#pragma unroll 1
        for (int ic = 0; ic < ICCH; ic++) {
            float in44[4][4];
#pragma unroll
            for (int iy = 0; iy < 4; iy++)
#pragma unroll
                for (int ix = 0; ix < 4; ix++)
                    in44[iy][ix] = patch[ic*324 + (qy*2 + iy)*18 + qx*2 + ix];
#pragma unroll
            for (int o = 0; o < 16; o++) {
                const float* wp = ws + (tg*16 + o)*144 + ic*9;
                float w0 = wp[0], w1 = wp[1], w2 = wp[2];
                float w3 = wp[3], w4 = wp[4], w5 = wp[5];
                float w6 = wp[6], w7 = wp[7], w8 = wp[8];
#pragma unroll
                for (int dy = 0; dy < 2; dy++)
#pragma unroll
                    for (int dx = 0; dx < 2; dx++) {
                        acc[dy*2 + dx][o] +=
                              w0*in44[dy  ][dx] + w1*in44[dy  ][dx+1] + w2*in44[dy  ][dx+2]
                            + w3*in44[dy+1][dx] + w4*in44[dy+1][dx+1] + w5*in44[dy+1][dx+2]
                            + w6*in44[dy+2][dx] + w7*in44[dy+2][dx+1] + w8*in44[dy+2][dx+2];
                    }
            }
        }
    }
#pragma unroll
    for (int o = 0; o < 16; o++) {
        int oc = tg*16 + o;
        float bb = bias[oc];
#pragma unroll
        for (int dy = 0; dy < 2; dy++)
#pragma unroll
            for (int dx = 0; dx < 2; dx++)
                out[(size_t)(b*DD + oc)*HW + (ty0 + qy*2 + dy)*64 + tx0 + qx*2 + dx] =
                    acc[dy*2 + dx][o] + bb;
    }
}

// ---------------------------------------------------------------------------
// Flash attention on tensor cores: mma.sync m16n8k16 bf16 with hi/lo split
// (3 terms: hi*hi + hi*lo + lo*hi ~ fp32 precision).
//
// Block: 64 queries, 8 warps. Warp w: rows R0=(w&3)*16, col-half C0=(w>>2)*32.
// SMEM bf16 tiles, stride 72 (144B rows -> ldmatrix conflict-free):
//   KH/KL [c][j]   (B frags for S via ldmatrix.trans)
//   VH/VL [c][j]   (B frags for PV via ldmatrix, n=c rows, k=j contiguous)
//   PH/PL [i][j]   (A frags for PV; also staging [c][i] for Q at start)
// Q A-fragments hoisted to registers for the whole block.
// ---------------------------------------------------------------------------
#define TILEB (64*72)                       // bf16 elements per tile
#define ATTN_SMEM (6*TILEB*2 + 2*128*4)     // 6 bf16 tiles + smax/ssum

__global__ __launch_bounds__(256) void k_attn_mma() {
    extern __shared__ char smraw[];
    __nv_bfloat16* KH = (__nv_bfloat16*)smraw;
    __nv_bfloat16* KL = KH + TILEB;
    __nv_bfloat16* VH = KH + 2*TILEB;
    __nv_bfloat16* VL = KH + 3*TILEB;
    __nv_bfloat16* PH = KH + 4*TILEB;   // also Q-hi staging [c][i]
    __nv_bfloat16* PL = KH + 5*TILEB;   // also Q-lo staging
    float* smax = (float*)(smraw + 6*TILEB*2);   // [8][16]
    float* ssum = smax + 128;                     // [8][16]

    int b  = blockIdx.y;
    int i0 = blockIdx.x * 64;
    int tid = threadIdx.x;
    int warp = tid >> 5, lane = tid & 31;
    int wr = warp & 3, wn = warp >> 2;
    int R0 = wr * 16, C0 = wn * 32;
    int g = lane >> 2, t = lane & 3;

    const float* Qg = g_q + (size_t)b*DD*NPIX;
    const float* Kg = g_k + (size_t)b*DD*NPIX;
    const float* Vg = g_v + (size_t)b*DD*NPIX;

    // ---- stage Q [c][i] into PH/PL, extract A-fragments to registers ----
#pragma unroll
    for (int r = 0; r < 16; r++) {
        int lin = tid + r * 256;
        int c = lin >> 6, ii = lin & 63;
        float qv = Qg[(size_t)c*NPIX + i0 + ii];
        __nv_bfloat16 h = __float2bfloat16(qv);
        PH[c*72 + ii] = h;
        PL[c*72 + ii] = __float2bfloat16(qv - __bfloat162float(h));
    }
    __syncthreads();

    unsigned qaH[4][4], qaL[4][4];
    {
        int krow = (lane & 7) + ((lane >> 4) << 3);
        int mcol = R0 + ((lane >> 3) & 1) * 8;
#pragma unroll
        for (int ks = 0; ks < 4; ks++) {
            ldsm_x4_t(qaH[ks], &PH[(ks*16 + krow)*72 + mcol]);
            ldsm_x4_t(qaL[ks], &PL[(ks*16 + krow)*72 + mcol]);
        }
    }

    float m0 = -1e30f, m1 = -1e30f, l0 = 0.f, l1 = 0.f;
    float oAcc[4][4];
#pragma unroll
    for (int ns = 0; ns < 4; ns++)
#pragma unroll
        for (int q = 0; q < 4; q++) oAcc[ns][q] = 0.f;

    // precomputed ldmatrix lane-addressing
    int kv_krow = (lane & 7) + (((lane >> 3) & 1) << 3);   // K (trans B): k within 16
    int kv_ncol = (lane >> 4) << 3;                        // + n-subblock
    int v_nrow  = (lane & 7) + ((lane >> 4) << 3);         // V (B): n row
    int v_kcol  = ((lane >> 3) & 1) << 3;                  // + k-subblock
    int p_row   = R0 + (lane & 15);                        // P (A)
    int p_kcol  = (lane >> 4) << 3;

    for (int j0 = 0; j0 < NPIX; j0 += 64) {
        __syncthreads();  // S1: previous tile consumed
        // ---- load K,V tile, bf16 hi/lo ----
#pragma unroll
        for (int r = 0; r < 16; r++) {
            int lin = tid + r * 256;
            int c = lin >> 6, jj = lin & 63;
            float kv = Kg[(size_t)c*NPIX + j0 + jj];
            float vv = Vg[(size_t)c*NPIX + j0 + jj];
            __nv_bfloat16 kh = __float2bfloat16(kv);
            __nv_bfloat16 vh = __float2bfloat16(vv);
            KH[c*72 + jj] = kh;
            KL[c*72 + jj] = __float2bfloat16(kv - __bfloat162float(kh));
            VH[c*72 + jj] = vh;
            VL[c*72 + jj] = __float2bfloat16(vv - __bfloat162float(vh));
        }
        __syncthreads();  // S2: K/V ready

        // ---- S = Q^T K ----
        float sAcc[4][4];
#pragma unroll
        for (int ns = 0; ns < 4; ns++)
#pragma unroll
            for (int q = 0; q < 4; q++) sAcc[ns][q] = 0.f;

#pragma unroll
        for (int ks = 0; ks < 4; ks++) {
            unsigned bh[2][4], bl[2][4];
            ldsm_x4_t(bh[0], &KH[(ks*16 + kv_krow)*72 + C0 + kv_ncol]);
            ldsm_x4_t(bh[1], &KH[(ks*16 + kv_krow)*72 + C0 + 16 + kv_ncol]);
            ldsm_x4_t(bl[0], &KL[(ks*16 + kv_krow)*72 + C0 + kv_ncol]);
            ldsm_x4_t(bl[1], &KL[(ks*16 + kv_krow)*72 + C0 + 16 + kv_ncol]);
#pragma unroll
            for (int h = 0; h < 2; h++) {
#pragma unroll
                for (int s = 0; s < 2; s++) {
                    mma_bf16(sAcc[h*2+s], qaH[ks], &bh[h][s*2]);
                    mma_bf16(sAcc[h*2+s], qaH[ks], &bl[h][s*2]);
                    mma_bf16(sAcc[h*2+s], qaL[ks], &bh[h][s*2]);
                }
            }
        }

        // ---- online softmax ----
        float rmax0 = sAcc[0][0], rmax1 = sAcc[0][2];
#pragma unroll
        for (int ns = 0; ns < 4; ns++) {
            rmax0 = fmaxf(rmax0, fmaxf(sAcc[ns][0], sAcc[ns][1]));
            rmax1 = fmaxf(rmax1, fmaxf(sAcc[ns][2], sAcc[ns][3]));
        }
        rmax0 = fmaxf(rmax0, __shfl_xor_sync(0xffffffffu, rmax0, 1));
        rmax0 = fmaxf(rmax0, __shfl_xor_sync(0xffffffffu, rmax0, 2));
        rmax1 = fmaxf(rmax1, __shfl_xor_sync(0xffffffffu, rmax1, 1));
        rmax1 = fmaxf(rmax1, __shfl_xor_sync(0xffffffffu, rmax1, 2));
        if (t == 0) {
            smax[warp*16 + g]     = rmax0;
            smax[warp*16 + 8 + g] = rmax1;
        }
        __syncthreads();  // S3: row maxima visible
        int pw = warp ^ 4;
        rmax0 = fmaxf(smax[warp*16 + g],     smax[pw*16 + g]);
        rmax1 = fmaxf(smax[warp*16 + 8 + g], smax[pw*16 + 8 + g]);
        float mn0 = fmaxf(m0, rmax0), mn1 = fmaxf(m1, rmax1);
        float sc0 = __expf(m0 - mn0), sc1 = __expf(m1 - mn1);
        m0 = mn0; m1 = mn1;

        float rs0 = 0.f, rs1 = 0.f;
#pragma unroll
        for (int ns = 0; ns < 4; ns++) {
            sAcc[ns][0] = __expf(sAcc[ns][0] - mn0);
            sAcc[ns][1] = __expf(sAcc[ns][1] - mn0);
            sAcc[ns][2] = __expf(sAcc[ns][2] - mn1);
            sAcc[ns][3] = __expf(sAcc[ns][3] - mn1);
            rs0 += sAcc[ns][0] + sAcc[ns][1];
            rs1 += sAcc[ns][2] + sAcc[ns][3];
        }
        rs0 += __shfl_xor_sync(0xffffffffu, rs0, 1);
        rs0 += __shfl_xor_sync(0xffffffffu, rs0, 2);
        rs1 += __shfl_xor_sync(0xffffffffu, rs1, 1);
        rs1 += __shfl_xor_sync(0xffffffffu, rs1, 2);
        if (t == 0) {
            ssum[warp*16 + g]     = rs0;
            ssum[warp*16 + 8 + g] = rs1;
        }

        // ---- quantize P to bf16 hi/lo, write [i][j] ----
#pragma unroll
        for (int ns = 0; ns < 4; ns++) {
            int col = C0 + ns*8 + 2*t;
            __nv_bfloat16 h0 = __float2bfloat16(sAcc[ns][0]);
            __nv_bfloat16 h1 = __float2bfloat16(sAcc[ns][1]);
            __nv_bfloat16 h2 = __float2bfloat16(sAcc[ns][2]);
            __nv_bfloat16 h3 = __float2bfloat16(sAcc[ns][3]);
            *(__nv_bfloat162*)&PH[(R0+g)*72 + col]   = __nv_bfloat162(h0, h1);
            *(__nv_bfloat162*)&PH[(R0+g+8)*72 + col] = __nv_bfloat162(h2, h3);
            __nv_bfloat16 e0 = __float2bfloat16(sAcc[ns][0] - __bfloat162float(h0));
            __nv_bfloat16 e1 = __float2bfloat16(sAcc[ns][1] - __bfloat162float(h1));
            __nv_bfloat16 e2 = __float2bfloat16(sAcc[ns][2] - __bfloat162float(h2));
            __nv_bfloat16 e3 = __float2bfloat16(sAcc[ns][3] - __bfloat162float(h3));
            *(__nv_bfloat162*)&PL[(R0+g)*72 + col]   = __nv_bfloat162(e0, e1);
            *(__nv_bfloat162*)&PL[(R0+g+8)*72 + col] = __nv_bfloat162(e2, e3);
        }
        __syncthreads();  // S4: row sums + P ready

        rs0 = ssum[warp*16 + g]     + ssum[pw*16 + g];
        rs1 = ssum[warp*16 + 8 + g] + ssum[pw*16 + 8 + g];
        l0 = l0*sc0 + rs0;
        l1 = l1*sc1 + rs1;
#pragma unroll
        for (int ns = 0; ns < 4; ns++) {
            oAcc[ns][0] *= sc0; oAcc[ns][1] *= sc0;
            oAcc[ns][2] *= sc1; oAcc[ns][3] *= sc1;
        }

        // ---- O += P V ----
#pragma unroll
        for (int ks = 0; ks < 4; ks++) {
            unsigned paH[4], paL[4], vbh[2][4], vbl[2][4];
            ldsm_x4(paH, &PH[p_row*72 + ks*16 + p_kcol]);
            ldsm_x4(paL, &PL[p_row*72 + ks*16 + p_kcol]);
            ldsm_x4(vbh[0], &VH[(C0 + v_nrow)*72 + ks*16 + v_kcol]);
            ldsm_x4(vbh[1], &VH[(C0 + 16 + v_nrow)*72 + ks*16 + v_kcol]);
            ldsm_x4(vbl[0], &VL[(C0 + v_nrow)*72 + ks*16 + v_kcol]);
            ldsm_x4(vbl[1], &VL[(C0 + 16 + v_nrow)*72 + ks*16 + v_kcol]);
#pragma unroll
            for (int h = 0; h < 2; h++) {
#pragma unroll
                for (int s = 0; s < 2; s++) {
                    mma_bf16(oAcc[h*2+s], paH, &vbh[h][s*2]);
                    mma_bf16(oAcc[h*2+s], paH, &vbl[h][s*2]);
                    mma_bf16(oAcc[h*2+s], paL, &vbh[h][s*2]);
                }
            }
        }
    }

    // ---- epilogue: normalize, write g_ao [c][i] ----
    float inv0 = 1.f / l0, inv1 = 1.f / l1;
#pragma unroll
    for (int ns = 0; ns < 4; ns++) {
        int c = C0 + ns*8 + 2*t;
        int ia = i0 + R0 + g, ib = ia + 8;
        g_ao[(size_t)(b*DD + c  )*NPIX + ia] = oAcc[ns][0] * inv0;
        g_ao[(size_t)(b*DD + c+1)*NPIX + ia] = oAcc[ns][1] * inv0;
        g_ao[(size_t)(b*DD + c  )*NPIX + ib] = oAcc[ns][2] * inv1;
        g_ao[(size_t)(b*DD + c+1)*NPIX + ib] = oAcc[ns][3] * inv1;
    }
}

// ---------------------------------------------------------------------------
// out-projection + residual + LayerNorm (round-0 proven)
// ---------------------------------------------------------------------------
__global__ __launch_bounds__(256) void k_outproj_ln(const float* __restrict__ x,
                                                    const float* __restrict__ w,
                                                    const float* __restrict__ bias,
                                                    const float* __restrict__ gamma,
                                                    const float* __restrict__ lnw,
                                                    const float* __restrict__ lnb,
                                                    float* __restrict__ out) {
    int b  = blockIdx.y;
    int p0 = blockIdx.x * 64;
    int tid = threadIdx.x;
    int tp = tid & 63, tg = tid >> 6;
    __shared__ float xs[16][65];
    __shared__ float ws[256][17];
    __shared__ float red[2][4][64];

    float acc[64];
#pragma unroll
    for (int i = 0; i < 64; i++) acc[i] = 0.f;

    for (int d0 = 0; d0 < DD; d0 += 16) {
        __syncthreads();
#pragma unroll
        for (int r = 0; r < 4; r++) {
            int lin = tid + r * 256;
            int cc = lin >> 6, pp = lin & 63;
            xs[cc][pp] = g_ao[(size_t)(b*DD + d0 + cc)*HW + p0 + pp];
        }
#pragma unroll
        for (int r = 0; r < 16; r++) {
            int lin = tid + r * 256;
            int co = lin >> 4, cc = lin & 15;
            ws[co][cc] = w[co*DD + d0 + cc];
        }
        __syncthreads();
#pragma unroll 4
        for (int cc = 0; cc < 16; cc++) {
            float xv = xs[cc][tp];
#pragma unroll
            for (int oo = 0; oo < 64; oo++)
                acc[oo] += ws[tg*64 + oo][cc] * xv;
        }
    }

    float gg = gamma[0];
    float s = 0.f, ss = 0.f;
#pragma unroll
    for (int oo = 0; oo < 64; oo++) {
        int co = tg*64 + oo;
        float v = gg * x[(size_t)(b*CIN + co)*HW + p0 + tp] + acc[oo] + bias[co];
        acc[oo] = v;
        s += v; ss += v*v;
    }
    red[0][tg][tp] = s;
    red[1][tg][tp] = ss;
    __syncthreads();
    float st  = red[0][0][tp] + red[0][1][tp] + red[0][2][tp] + red[0][3][tp];
    float sst = red[1][0][tp] + red[1][1][tp] + red[1][2][tp] + red[1][3][tp];
    float mu  = st * (1.f/256.f);
    float var = sst * (1.f/256.f) - mu*mu;
    float rstd = rsqrtf(var + 1e-5f);
#pragma unroll
    for (int oo = 0; oo < 64; oo++) {
        int co = tg*64 + oo;
        out[(size_t)(b*CIN + co)*HW + p0 + tp] = (acc[oo] - mu) * rstd * lnw[co] + lnb[co];
    }
}

// ---------------------------------------------------------------------------
extern "C" void kernel_launch(void* const* d_in, const int* in_sizes, int n_in,
                              void* d_out, int out_size) {
    const float* x     = (const float*)d_in[0];
    const float* w_in  = (const float*)d_in[1];
    const float* b_in  = (const float*)d_in[2];
    const float* wq    = (const float*)d_in[3];
    const float* bq    = (const float*)d_in[4];
    const float* wk    = (const float*)d_in[5];
    const float* bk    = (const float*)d_in[6];
    const float* wv    = (const float*)d_in[7];
    const float* bv    = (const float*)d_in[8];
    const float* w_out = (const float*)d_in[9];
    const float* b_out = (const float*)d_in[10];
    const float* gamma = (const float*)d_in[11];
    const float* ln_w  = (const float*)d_in[12];
    const float* ln_b  = (const float*)d_in[13];
    float* out = (float*)d_out;

    cudaFuncSetAttribute(k_conv3x3,  cudaFuncAttributeMaxDynamicSharedMemorySize, CONV_SMEM);
    cudaFuncSetAttribute(k_attn_mma, cudaFuncAttributeMaxDynamicSharedMemorySize, ATTN_SMEM);

    k_inproj<<<dim3(64, BATCH), 256>>>(x, w_in, b_in);
    k_conv3x3<<<dim3(4, 4, BATCH*3), 256, CONV_SMEM>>>(wq, bq, wk, bk, wv, bv);
    k_attn_mma<<<dim3(64, BATCH), 256, ATTN_SMEM>>>();
    k_outproj_ln<<<dim3(64, BATCH), 256>>>(x, w_out, b_out, gamma, ln_w, ln_b, out);
}

// round 5
// speedup vs baseline: 3.6278x; 1.1651x over previous
#include <cuda_runtime.h>
#include <cuda_bf16.h>
#include <math.h>

#define BATCH 4
#define CIN   256
#define DD    64
#define HW    4096
#define NPIX  4096

// scratch (no cudaMalloc allowed)
__device__ float g_att[BATCH*DD*HW];   // in-projection output
__device__ float g_ao[BATCH*DD*HW];    // attention output
// q/k/v pre-split to bf16 hi/lo by the conv epilogue
__device__ __nv_bfloat16 g_qH[BATCH*DD*HW];
__device__ __nv_bfloat16 g_qL[BATCH*DD*HW];
__device__ __nv_bfloat16 g_kH[BATCH*DD*HW];
__device__ __nv_bfloat16 g_kL[BATCH*DD*HW];
__device__ __nv_bfloat16 g_vH[BATCH*DD*HW];
__device__ __nv_bfloat16 g_vL[BATCH*DD*HW];

// ---------------------------------------------------------------------------
// mma / ldmatrix helpers
// ---------------------------------------------------------------------------
__device__ __forceinline__ void ldsm_x4(unsigned* r, const void* p) {
    unsigned a = (unsigned)__cvta_generic_to_shared(p);
    asm volatile("ldmatrix.sync.aligned.m8n8.x4.shared.b16 {%0,%1,%2,%3}, [%4];"
        : "=r"(r[0]), "=r"(r[1]), "=r"(r[2]), "=r"(r[3]) : "r"(a));
}
__device__ __forceinline__ void ldsm_x4_t(unsigned* r, const void* p) {
    unsigned a = (unsigned)__cvta_generic_to_shared(p);
    asm volatile("ldmatrix.sync.aligned.m8n8.x4.trans.shared.b16 {%0,%1,%2,%3}, [%4];"
        : "=r"(r[0]), "=r"(r[1]), "=r"(r[2]), "=r"(r[3]) : "r"(a));
}
__device__ __forceinline__ void mma_bf16(float* c, const unsigned* a, const unsigned* b) {
    asm volatile("mma.sync.aligned.m16n8k16.row.col.f32.bf16.bf16.f32 "
        "{%0,%1,%2,%3}, {%4,%5,%6,%7}, {%8,%9}, {%0,%1,%2,%3};"
        : "+f"(c[0]), "+f"(c[1]), "+f"(c[2]), "+f"(c[3])
        : "r"(a[0]), "r"(a[1]), "r"(a[2]), "r"(a[3]), "r"(b[0]), "r"(b[1]));
}

// ---------------------------------------------------------------------------
// 1x1 in-projection (round-0 proven)
// ---------------------------------------------------------------------------
__global__ __launch_bounds__(256) void k_inproj(const float* __restrict__ x,
                                                const float* __restrict__ w,
                                                const float* __restrict__ bias) {
    int b  = blockIdx.y;
    int p0 = blockIdx.x * 64;
    int tid = threadIdx.x;
    int tp = tid & 63, tg = tid >> 6;
    __shared__ float xs[32][65];
    __shared__ float ws[64][33];
    float acc[16];
#pragma unroll
    for (int i = 0; i < 16; i++) acc[i] = 0.f;

    for (int c0 = 0; c0 < CIN; c0 += 32) {
        __syncthreads();
#pragma unroll
        for (int r = 0; r < 8; r++) {
            int lin = tid + r * 256;
            int cc = lin >> 6, pp = lin & 63;
            xs[cc][pp] = x[(size_t)(b*CIN + c0 + cc)*HW + p0 + pp];
        }
#pragma unroll
        for (int r = 0; r < 8; r++) {
            int lin = tid + r * 256;
            int dd = lin >> 5, cc = lin & 31;
            ws[dd][cc] = w[dd*CIN + c0 + cc];
        }
        __syncthreads();
#pragma unroll 8
        for (int cc = 0; cc < 32; cc++) {
            float xv = xs[cc][tp];
#pragma unroll
            for (int dd = 0; dd < 16; dd++)
                acc[dd] += ws[tg*16 + dd][cc] * xv;
        }
    }
#pragma unroll
    for (int dd = 0; dd < 16; dd++) {
        int d = tg*16 + dd;
        g_att[(size_t)(b*DD + d)*HW + p0 + tp] = acc[dd] + bias[d];
    }
}

// ---------------------------------------------------------------------------
// 3x3 conv (pad 1), D=64 -> D=64, q/k/v via blockIdx.z.
// Epilogue writes bf16 hi/lo splits (the only consumer is tensor-core attn).
// ---------------------------------------------------------------------------
#define ICCH 16
#define CONV_SMEM ((ICCH*324 + 64*ICCH*9) * 4)

__global__ __launch_bounds__(256) void k_conv3x3(const float* __restrict__ wq, const float* __restrict__ bq,
                                                 const float* __restrict__ wk, const float* __restrict__ bk,
                                                 const float* __restrict__ wv, const float* __restrict__ bv) {
    extern __shared__ float sm[];
    float* patch = sm;                  // [ICCH][18][18]
    float* ws    = sm + ICCH*324;       // [64][ICCH][9]

    int b     = blockIdx.z / 3;
    int which = blockIdx.z % 3;
    const float* w    = (which == 0) ? wq : (which == 1) ? wk : wv;
    const float* bias = (which == 0) ? bq : (which == 1) ? bk : bv;
    __nv_bfloat16* outH = (which == 0) ? g_qH : (which == 1) ? g_kH : g_vH;
    __nv_bfloat16* outL = (which == 0) ? g_qL : (which == 1) ? g_kL : g_vL;

    int ty0 = blockIdx.y * 16, tx0 = blockIdx.x * 16;
    int tid = threadIdx.x;
    int tq = tid & 63, tg = tid >> 6;
    int qx = tq & 7, qy = tq >> 3;

    float acc[4][16];
#pragma unroll
    for (int p = 0; p < 4; p++)
#pragma unroll
        for (int o = 0; o < 16; o++) acc[p][o] = 0.f;

    for (int c0 = 0; c0 < DD; c0 += ICCH) {
        __syncthreads();
        for (int r = 0; r < 21; r++) {
            int lin = tid + r * 256;
            if (lin < ICCH*324) {
                int ic = lin / 324, rem = lin % 324;
                int py = rem / 18, px = rem % 18;
                int gy = ty0 + py - 1, gx = tx0 + px - 1;
                float v = 0.f;
                if (gy >= 0 && gy < 64 && gx >= 0 && gx < 64)
                    v = g_att[(size_t)(b*DD + c0 + ic)*HW + gy*64 + gx];
                patch[lin] = v;
            }
        }
        for (int r = 0; r < 36; r++) {
            int lin = tid + r * 256;
            int oc = lin / 144, rem = lin % 144;
            int ic = rem / 9, tap = rem % 9;
            ws[lin] = w[oc*576 + (c0 + ic)*9 + tap];
        }
        __syncthreads();

#pragma unroll 1
        for (int ic = 0; ic < ICCH; ic++) {
            float in44[4][4];
#pragma unroll
            for (int iy = 0; iy < 4; iy++)
#pragma unroll
                for (int ix = 0; ix < 4; ix++)
                    in44[iy][ix] = patch[ic*324 + (qy*2 + iy)*18 + qx*2 + ix];
#pragma unroll
            for (int o = 0; o < 16; o++) {
                const float* wp = ws + (tg*16 + o)*144 + ic*9;
                float w0 = wp[0], w1 = wp[1], w2 = wp[2];
                float w3 = wp[3], w4 = wp[4], w5 = wp[5];
                float w6 = wp[6], w7 = wp[7], w8 = wp[8];
#pragma unroll
                for (int dy = 0; dy < 2; dy++)
#pragma unroll
                    for (int dx = 0; dx < 2; dx++) {
                        acc[dy*2 + dx][o] +=
                              w0*in44[dy  ][dx] + w1*in44[dy  ][dx+1] + w2*in44[dy  ][dx+2]
                            + w3*in44[dy+1][dx] + w4*in44[dy+1][dx+1] + w5*in44[dy+1][dx+2]
                            + w6*in44[dy+2][dx] + w7*in44[dy+2][dx+1] + w8*in44[dy+2][dx+2];
                    }
            }
        }
    }
#pragma unroll
    for (int o = 0; o < 16; o++) {
        int oc = tg*16 + o;
        float bb = bias[oc];
#pragma unroll
        for (int dy = 0; dy < 2; dy++)
#pragma unroll
            for (int dx = 0; dx < 2; dx++) {
                float v = acc[dy*2 + dx][o] + bb;
                size_t idx = (size_t)(b*DD + oc)*HW + (ty0 + qy*2 + dy)*64 + tx0 + qx*2 + dx;
                __nv_bfloat16 h = __float2bfloat16(v);
                outH[idx] = h;
                outL[idx] = __float2bfloat16(v - __bfloat162float(h));
            }
    }
}

// ---------------------------------------------------------------------------
// Flash attention on tensor cores, bf16 hi/lo pre-split in global memory.
// Tile loads are pure uint4 copies (global bf16 -> smem bf16).
// ---------------------------------------------------------------------------
#define TILEB (64*72)                       // bf16 elements per tile
#define ATTN_SMEM (6*TILEB*2 + 2*128*4)     // 6 bf16 tiles + smax/ssum

__global__ __launch_bounds__(256) void k_attn_mma() {
    extern __shared__ char smraw[];
    __nv_bfloat16* KH = (__nv_bfloat16*)smraw;
    __nv_bfloat16* KL = KH + TILEB;
    __nv_bfloat16* VH = KH + 2*TILEB;
    __nv_bfloat16* VL = KH + 3*TILEB;
    __nv_bfloat16* PH = KH + 4*TILEB;   // also Q-hi staging [c][i]
    __nv_bfloat16* PL = KH + 5*TILEB;   // also Q-lo staging
    float* smax = (float*)(smraw + 6*TILEB*2);   // [8][16]
    float* ssum = smax + 128;                     // [8][16]

    int b  = blockIdx.y;
    int i0 = blockIdx.x * 64;
    int tid = threadIdx.x;
    int warp = tid >> 5, lane = tid & 31;
    int wr = warp & 3, wn = warp >> 2;
    int R0 = wr * 16, C0 = wn * 32;
    int g = lane >> 2, t = lane & 3;

    size_t base = (size_t)b*DD*NPIX;

    // ---- stage Q [c][i] into PH/PL (vectorized), extract A-fragments ----
    {
        int c = tid >> 3, v8 = tid & 7;          // 256 threads = 32 rows x 8 vec
#pragma unroll
        for (int r = 0; r < 2; r++) {
            int cc = c + r*32;
            const uint4* sh = (const uint4*)&g_qH[base + (size_t)cc*NPIX + i0];
            const uint4* sl = (const uint4*)&g_qL[base + (size_t)cc*NPIX + i0];
            *((uint4*)&PH[cc*72] + v8) = sh[v8];
            *((uint4*)&PL[cc*72] + v8) = sl[v8];
        }
    }
    __syncthreads();

    unsigned qaH[4][4], qaL[4][4];
    {
        int krow = (lane & 7) + ((lane >> 4) << 3);
        int mcol = R0 + ((lane >> 3) & 1) * 8;
#pragma unroll
        for (int ks = 0; ks < 4; ks++) {
            ldsm_x4_t(qaH[ks], &PH[(ks*16 + krow)*72 + mcol]);
            ldsm_x4_t(qaL[ks], &PL[(ks*16 + krow)*72 + mcol]);
        }
    }

    float m0 = -1e30f, m1 = -1e30f, l0 = 0.f, l1 = 0.f;
    float oAcc[4][4];
#pragma unroll
    for (int ns = 0; ns < 4; ns++)
#pragma unroll
        for (int q = 0; q < 4; q++) oAcc[ns][q] = 0.f;

    // precomputed ldmatrix lane-addressing
    int kv_krow = (lane & 7) + (((lane >> 3) & 1) << 3);
    int kv_ncol = (lane >> 4) << 3;
    int v_nrow  = (lane & 7) + ((lane >> 4) << 3);
    int v_kcol  = ((lane >> 3) & 1) << 3;
    int p_row   = R0 + (lane & 15);
    int p_kcol  = (lane >> 4) << 3;

    int cpy_c = tid >> 3, cpy_v = tid & 7;       // tile-copy addressing

    for (int j0 = 0; j0 < NPIX; j0 += 64) {
        __syncthreads();  // S1: previous tile consumed
        // ---- copy K,V tile (bf16, vectorized) ----
#pragma unroll
        for (int r = 0; r < 2; r++) {
            int cc = cpy_c + r*32;
            size_t go = base + (size_t)cc*NPIX + j0;
            *((uint4*)&KH[cc*72] + cpy_v) = *((const uint4*)&g_kH[go] + cpy_v);
            *((uint4*)&KL[cc*72] + cpy_v) = *((const uint4*)&g_kL[go] + cpy_v);
            *((uint4*)&VH[cc*72] + cpy_v) = *((const uint4*)&g_vH[go] + cpy_v);
            *((uint4*)&VL[cc*72] + cpy_v) = *((const uint4*)&g_vL[go] + cpy_v);
        }
        __syncthreads();  // S2: K/V ready

        // ---- S = Q^T K ----
        float sAcc[4][4];
#pragma unroll
        for (int ns = 0; ns < 4; ns++)
#pragma unroll
            for (int q = 0; q < 4; q++) sAcc[ns][q] = 0.f;

#pragma unroll
        for (int ks = 0; ks < 4; ks++) {
            unsigned bh[2][4], bl[2][4];
            ldsm_x4_t(bh[0], &KH[(ks*16 + kv_krow)*72 + C0 + kv_ncol]);
            ldsm_x4_t(bh[1], &KH[(ks*16 + kv_krow)*72 + C0 + 16 + kv_ncol]);
            ldsm_x4_t(bl[0], &KL[(ks*16 + kv_krow)*72 + C0 + kv_ncol]);
            ldsm_x4_t(bl[1], &KL[(ks*16 + kv_krow)*72 + C0 + 16 + kv_ncol]);
#pragma unroll
            for (int h = 0; h < 2; h++) {
#pragma unroll
                for (int s = 0; s < 2; s++) {
                    mma_bf16(sAcc[h*2+s], qaH[ks], &bh[h][s*2]);
                    mma_bf16(sAcc[h*2+s], qaH[ks], &bl[h][s*2]);
                    mma_bf16(sAcc[h*2+s], qaL[ks], &bh[h][s*2]);
                }
            }
        }

        // ---- online softmax ----
        float rmax0 = sAcc[0][0], rmax1 = sAcc[0][2];
#pragma unroll
        for (int ns = 0; ns < 4; ns++) {
            rmax0 = fmaxf(rmax0, fmaxf(sAcc[ns][0], sAcc[ns][1]));
            rmax1 = fmaxf(rmax1, fmaxf(sAcc[ns][2], sAcc[ns][3]));
        }
        rmax0 = fmaxf(rmax0, __shfl_xor_sync(0xffffffffu, rmax0, 1));
        rmax0 = fmaxf(rmax0, __shfl_xor_sync(0xffffffffu, rmax0, 2));
        rmax1 = fmaxf(rmax1, __shfl_xor_sync(0xffffffffu, rmax1, 1));
        rmax1 = fmaxf(rmax1, __shfl_xor_sync(0xffffffffu, rmax1, 2));
        if (t == 0) {
            smax[warp*16 + g]     = rmax0;
            smax[warp*16 + 8 + g] = rmax1;
        }
        __syncthreads();  // S3: row maxima visible
        int pw = warp ^ 4;
        rmax0 = fmaxf(smax[warp*16 + g],     smax[pw*16 + g]);
        rmax1 = fmaxf(smax[warp*16 + 8 + g], smax[pw*16 + 8 + g]);
        float mn0 = fmaxf(m0, rmax0), mn1 = fmaxf(m1, rmax1);
        float sc0 = __expf(m0 - mn0), sc1 = __expf(m1 - mn1);
        m0 = mn0; m1 = mn1;

        float rs0 = 0.f, rs1 = 0.f;
#pragma unroll
        for (int ns = 0; ns < 4; ns++) {
            sAcc[ns][0] = __expf(sAcc[ns][0] - mn0);
            sAcc[ns][1] = __expf(sAcc[ns][1] - mn0);
            sAcc[ns][2] = __expf(sAcc[ns][2] - mn1);
            sAcc[ns][3] = __expf(sAcc[ns][3] - mn1);
            rs0 += sAcc[ns][0] + sAcc[ns][1];
            rs1 += sAcc[ns][2] + sAcc[ns][3];
        }
        rs0 += __shfl_xor_sync(0xffffffffu, rs0, 1);
        rs0 += __shfl_xor_sync(0xffffffffu, rs0, 2);
        rs1 += __shfl_xor_sync(0xffffffffu, rs1, 1);
        rs1 += __shfl_xor_sync(0xffffffffu, rs1, 2);
        if (t == 0) {
            ssum[warp*16 + g]     = rs0;
            ssum[warp*16 + 8 + g] = rs1;
        }

        // ---- quantize P to bf16 hi/lo, write [i][j] ----
#pragma unroll
        for (int ns = 0; ns < 4; ns++) {
            int col = C0 + ns*8 + 2*t;
            __nv_bfloat16 h0 = __float2bfloat16(sAcc[ns][0]);
            __nv_bfloat16 h1 = __float2bfloat16(sAcc[ns][1]);
            __nv_bfloat16 h2 = __float2bfloat16(sAcc[ns][2]);
            __nv_bfloat16 h3 = __float2bfloat16(sAcc[ns][3]);
            *(__nv_bfloat162*)&PH[(R0+g)*72 + col]   = __nv_bfloat162(h0, h1);
            *(__nv_bfloat162*)&PH[(R0+g+8)*72 + col] = __nv_bfloat162(h2, h3);
            __nv_bfloat16 e0 = __float2bfloat16(sAcc[ns][0] - __bfloat162float(h0));
            __nv_bfloat16 e1 = __float2bfloat16(sAcc[ns][1] - __bfloat162float(h1));
            __nv_bfloat16 e2 = __float2bfloat16(sAcc[ns][2] - __bfloat162float(h2));
            __nv_bfloat16 e3 = __float2bfloat16(sAcc[ns][3] - __bfloat162float(h3));
            *(__nv_bfloat162*)&PL[(R0+g)*72 + col]   = __nv_bfloat162(e0, e1);
            *(__nv_bfloat162*)&PL[(R0+g+8)*72 + col] = __nv_bfloat162(e2, e3);
        }
        __syncthreads();  // S4: row sums + P ready

        rs0 = ssum[warp*16 + g]     + ssum[pw*16 + g];
        rs1 = ssum[warp*16 + 8 + g] + ssum[pw*16 + 8 + g];
        l0 = l0*sc0 + rs0;
        l1 = l1*sc1 + rs1;
#pragma unroll
        for (int ns = 0; ns < 4; ns++) {
            oAcc[ns][0] *= sc0; oAcc[ns][1] *= sc0;
            oAcc[ns][2] *= sc1; oAcc[ns][3] *= sc1;
        }

        // ---- O += P V ----
#pragma unroll
        for (int ks = 0; ks < 4; ks++) {
            unsigned paH[4], paL[4], vbh[2][4], vbl[2][4];
            ldsm_x4(paH, &PH[p_row*72 + ks*16 + p_kcol]);
            ldsm_x4(paL, &PL[p_row*72 + ks*16 + p_kcol]);
            ldsm_x4(vbh[0], &VH[(C0 + v_nrow)*72 + ks*16 + v_kcol]);
            ldsm_x4(vbh[1], &VH[(C0 + 16 + v_nrow)*72 + ks*16 + v_kcol]);
            ldsm_x4(vbl[0], &VL[(C0 + v_nrow)*72 + ks*16 + v_kcol]);
            ldsm_x4(vbl[1], &VL[(C0 + 16 + v_nrow)*72 + ks*16 + v_kcol]);
#pragma unroll
            for (int h = 0; h < 2; h++) {
#pragma unroll
                for (int s = 0; s < 2; s++) {
                    mma_bf16(oAcc[h*2+s], paH, &vbh[h][s*2]);
                    mma_bf16(oAcc[h*2+s], paH, &vbl[h][s*2]);
                    mma_bf16(oAcc[h*2+s], paL, &vbh[h][s*2]);
                }
            }
        }
    }

    // ---- epilogue: normalize, write g_ao [c][i] ----
    float inv0 = 1.f / l0, inv1 = 1.f / l1;
#pragma unroll
    for (int ns = 0; ns < 4; ns++) {
        int c = C0 + ns*8 + 2*t;
        int ia = i0 + R0 + g, ib = ia + 8;
        g_ao[(size_t)(b*DD + c  )*NPIX + ia] = oAcc[ns][0] * inv0;
        g_ao[(size_t)(b*DD + c+1)*NPIX + ia] = oAcc[ns][1] * inv0;
        g_ao[(size_t)(b*DD + c  )*NPIX + ib] = oAcc[ns][2] * inv1;
        g_ao[(size_t)(b*DD + c+1)*NPIX + ib] = oAcc[ns][3] * inv1;
    }
}

// ---------------------------------------------------------------------------
// out-projection + residual + LayerNorm (round-0 proven)
// ---------------------------------------------------------------------------
__global__ __launch_bounds__(256) void k_outproj_ln(const float* __restrict__ x,
                                                    const float* __restrict__ w,
                                                    const float* __restrict__ bias,
                                                    const float* __restrict__ gamma,
                                                    const float* __restrict__ lnw,
                                                    const float* __restrict__ lnb,
                                                    float* __restrict__ out) {
    int b  = blockIdx.y;
    int p0 = blockIdx.x * 64;
    int tid = threadIdx.x;
    int tp = tid & 63, tg = tid >> 6;
    __shared__ float xs[16][65];
    __shared__ float ws[256][17];
    __shared__ float red[2][4][64];

    float acc[64];
#pragma unroll
    for (int i = 0; i < 64; i++) acc[i] = 0.f;

    for (int d0 = 0; d0 < DD; d0 += 16) {
        __syncthreads();
#pragma unroll
        for (int r = 0; r < 4; r++) {
            int lin = tid + r * 256;
            int cc = lin >> 6, pp = lin & 63;
            xs[cc][pp] = g_ao[(size_t)(b*DD + d0 + cc)*HW + p0 + pp];
        }
#pragma unroll
        for (int r = 0; r < 16; r++) {
            int lin = tid + r * 256;
            int co = lin >> 4, cc = lin & 15;
            ws[co][cc] = w[co*DD + d0 + cc];
        }
        __syncthreads();
#pragma unroll 4
        for (int cc = 0; cc < 16; cc++) {
            float xv = xs[cc][tp];
#pragma unroll
            for (int oo = 0; oo < 64; oo++)
                acc[oo] += ws[tg*64 + oo][cc] * xv;
        }
    }

    float gg = gamma[0];
    float s = 0.f, ss = 0.f;
#pragma unroll
    for (int oo = 0; oo < 64; oo++) {
        int co = tg*64 + oo;
        float v = gg * x[(size_t)(b*CIN + co)*HW + p0 + tp] + acc[oo] + bias[co];
        acc[oo] = v;
        s += v; ss += v*v;
    }
    red[0][tg][tp] = s;
    red[1][tg][tp] = ss;
    __syncthreads();
    float st  = red[0][0][tp] + red[0][1][tp] + red[0][2][tp] + red[0][3][tp];
    float sst = red[1][0][tp] + red[1][1][tp] + red[1][2][tp] + red[1][3][tp];
    float mu  = st * (1.f/256.f);
    float var = sst * (1.f/256.f) - mu*mu;
    float rstd = rsqrtf(var + 1e-5f);
#pragma unroll
    for (int oo = 0; oo < 64; oo++) {
        int co = tg*64 + oo;
        out[(size_t)(b*CIN + co)*HW + p0 + tp] = (acc[oo] - mu) * rstd * lnw[co] + lnb[co];
    }
}

// ---------------------------------------------------------------------------
extern "C" void kernel_launch(void* const* d_in, const int* in_sizes, int n_in,
                              void* d_out, int out_size) {
    const float* x     = (const float*)d_in[0];
    const float* w_in  = (const float*)d_in[1];
    const float* b_in  = (const float*)d_in[2];
    const float* wq    = (const float*)d_in[3];
    const float* bq    = (const float*)d_in[4];
    const float* wk    = (const float*)d_in[5];
    const float* bk    = (const float*)d_in[6];
    const float* wv    = (const float*)d_in[7];
    const float* bv    = (const float*)d_in[8];
    const float* w_out = (const float*)d_in[9];
    const float* b_out = (const float*)d_in[10];
    const float* gamma = (const float*)d_in[11];
    const float* ln_w  = (const float*)d_in[12];
    const float* ln_b  = (const float*)d_in[13];
    float* out = (float*)d_out;

    cudaFuncSetAttribute(k_conv3x3,  cudaFuncAttributeMaxDynamicSharedMemorySize, CONV_SMEM);
    cudaFuncSetAttribute(k_attn_mma, cudaFuncAttributeMaxDynamicSharedMemorySize, ATTN_SMEM);

    k_inproj<<<dim3(64, BATCH), 256>>>(x, w_in, b_in);
    k_conv3x3<<<dim3(4, 4, BATCH*3), 256, CONV_SMEM>>>(wq, bq, wk, bk, wv, bv);
    k_attn_mma<<<dim3(64, BATCH), 256, ATTN_SMEM>>>();
    k_outproj_ln<<<dim3(64, BATCH), 256>>>(x, w_out, b_out, gamma, ln_w, ln_b, out);
}

// round 6
// speedup vs baseline: 3.7042x; 1.0211x over previous
#include <cuda_runtime.h>
#include <cuda_bf16.h>
#include <math.h>

#define BATCH 4
#define CIN   256
#define DD    64
#define HW    4096
#define NPIX  4096
#define QTILE 128

// scratch (no cudaMalloc allowed)
__device__ float g_att[BATCH*DD*HW];   // in-projection output
__device__ float g_ao[BATCH*DD*HW];    // attention output
// q/k/v pre-split to bf16 hi/lo by the conv epilogue
__device__ __nv_bfloat16 g_qH[BATCH*DD*HW];
__device__ __nv_bfloat16 g_qL[BATCH*DD*HW];
__device__ __nv_bfloat16 g_kH[BATCH*DD*HW];
__device__ __nv_bfloat16 g_kL[BATCH*DD*HW];
__device__ __nv_bfloat16 g_vH[BATCH*DD*HW];
__device__ __nv_bfloat16 g_vL[BATCH*DD*HW];

// ---------------------------------------------------------------------------
// mma / ldmatrix / cp.async helpers
// ---------------------------------------------------------------------------
__device__ __forceinline__ void ldsm_x4(unsigned* r, const void* p) {
    unsigned a = (unsigned)__cvta_generic_to_shared(p);
    asm volatile("ldmatrix.sync.aligned.m8n8.x4.shared.b16 {%0,%1,%2,%3}, [%4];"
        : "=r"(r[0]), "=r"(r[1]), "=r"(r[2]), "=r"(r[3]) : "r"(a));
}
__device__ __forceinline__ void ldsm_x4_t(unsigned* r, const void* p) {
    unsigned a = (unsigned)__cvta_generic_to_shared(p);
    asm volatile("ldmatrix.sync.aligned.m8n8.x4.trans.shared.b16 {%0,%1,%2,%3}, [%4];"
        : "=r"(r[0]), "=r"(r[1]), "=r"(r[2]), "=r"(r[3]) : "r"(a));
}
__device__ __forceinline__ void mma_bf16(float* c, const unsigned* a, const unsigned* b) {
    asm volatile("mma.sync.aligned.m16n8k16.row.col.f32.bf16.bf16.f32 "
        "{%0,%1,%2,%3}, {%4,%5,%6,%7}, {%8,%9}, {%0,%1,%2,%3};"
        : "+f"(c[0]), "+f"(c[1]), "+f"(c[2]), "+f"(c[3])
        : "r"(a[0]), "r"(a[1]), "r"(a[2]), "r"(a[3]), "r"(b[0]), "r"(b[1]));
}
__device__ __forceinline__ void cp16(void* smem, const void* gmem) {
    unsigned a = (unsigned)__cvta_generic_to_shared(smem);
    asm volatile("cp.async.cg.shared.global [%0], [%1], 16;" :: "r"(a), "l"(gmem));
}
__device__ __forceinline__ void packhl(float a, float b, unsigned &h, unsigned &l) {
    __nv_bfloat16 ha = __float2bfloat16(a), hb = __float2bfloat16(b);
    __nv_bfloat162 hh(ha, hb);
    h = *(unsigned*)&hh;
    __nv_bfloat162 ll(__float2bfloat16(a - __bfloat162float(ha)),
                      __float2bfloat16(b - __bfloat162float(hb)));
    l = *(unsigned*)&ll;
}

// ---------------------------------------------------------------------------
// 1x1 in-projection (proven)
// ---------------------------------------------------------------------------
__global__ __launch_bounds__(256) void k_inproj(const float* __restrict__ x,
                                                const float* __restrict__ w,
                                                const float* __restrict__ bias) {
    int b  = blockIdx.y;
    int p0 = blockIdx.x * 64;
    int tid = threadIdx.x;
    int tp = tid & 63, tg = tid >> 6;
    __shared__ float xs[32][65];
    __shared__ float ws[64][33];
    float acc[16];
#pragma unroll
    for (int i = 0; i < 16; i++) acc[i] = 0.f;

    for (int c0 = 0; c0 < CIN; c0 += 32) {
        __syncthreads();
#pragma unroll
        for (int r = 0; r < 8; r++) {
            int lin = tid + r * 256;
            int cc = lin >> 6, pp = lin & 63;
            xs[cc][pp] = x[(size_t)(b*CIN + c0 + cc)*HW + p0 + pp];
        }
#pragma unroll
        for (int r = 0; r < 8; r++) {
            int lin = tid + r * 256;
            int dd = lin >> 5, cc = lin & 31;
            ws[dd][cc] = w[dd*CIN + c0 + cc];
        }
        __syncthreads();
#pragma unroll 8
        for (int cc = 0; cc < 32; cc++) {
            float xv = xs[cc][tp];
#pragma unroll
            for (int dd = 0; dd < 16; dd++)
                acc[dd] += ws[tg*16 + dd][cc] * xv;
        }
    }
#pragma unroll
    for (int dd = 0; dd < 16; dd++) {
        int d = tg*16 + dd;
        g_att[(size_t)(b*DD + d)*HW + p0 + tp] = acc[dd] + bias[d];
    }
}

// ---------------------------------------------------------------------------
// 3x3 conv (pad 1), writes bf16 hi/lo splits (proven)
// ---------------------------------------------------------------------------
#define ICCH 16
#define CONV_SMEM ((ICCH*324 + 64*ICCH*9) * 4)

__global__ __launch_bounds__(256) void k_conv3x3(const float* __restrict__ wq, const float* __restrict__ bq,
                                                 const float* __restrict__ wk, const float* __restrict__ bk,
                                                 const float* __restrict__ wv, const float* __restrict__ bv) {
    extern __shared__ float sm[];
    float* patch = sm;                  // [ICCH][18][18]
    float* ws    = sm + ICCH*324;       // [64][ICCH][9]

    int b     = blockIdx.z / 3;
    int which = blockIdx.z % 3;
    const float* w    = (which == 0) ? wq : (which == 1) ? wk : wv;
    const float* bias = (which == 0) ? bq : (which == 1) ? bk : bv;
    __nv_bfloat16* outH = (which == 0) ? g_qH : (which == 1) ? g_kH : g_vH;
    __nv_bfloat16* outL = (which == 0) ? g_qL : (which == 1) ? g_kL : g_vL;

    int ty0 = blockIdx.y * 16, tx0 = blockIdx.x * 16;
    int tid = threadIdx.x;
    int tq = tid & 63, tg = tid >> 6;
    int qx = tq & 7, qy = tq >> 3;

    float acc[4][16];
#pragma unroll
    for (int p = 0; p < 4; p++)
#pragma unroll
        for (int o = 0; o < 16; o++) acc[p][o] = 0.f;

    for (int c0 = 0; c0 < DD; c0 += ICCH) {
        __syncthreads();
        for (int r = 0; r < 21; r++) {
            int lin = tid + r * 256;
            if (lin < ICCH*324) {
                int ic = lin / 324, rem = lin % 324;
                int py = rem / 18, px = rem % 18;
                int gy = ty0 + py - 1, gx = tx0 + px - 1;
                float v = 0.f;
                if (gy >= 0 && gy < 64 && gx >= 0 && gx < 64)
                    v = g_att[(size_t)(b*DD + c0 + ic)*HW + gy*64 + gx];
                patch[lin] = v;
            }
        }
        for (int r = 0; r < 36; r++) {
            int lin = tid + r * 256;
            int oc = lin / 144, rem = lin % 144;
            int ic = rem / 9, tap = rem % 9;
            ws[lin] = w[oc*576 + (c0 + ic)*9 + tap];
        }
        __syncthreads();

#pragma unroll 1
        for (int ic = 0; ic < ICCH; ic++) {
            float in44[4][4];
#pragma unroll
            for (int iy = 0; iy < 4; iy++)
#pragma unroll
                for (int ix = 0; ix < 4; ix++)
                    in44[iy][ix] = patch[ic*324 + (qy*2 + iy)*18 + qx*2 + ix];
#pragma unroll
            for (int o = 0; o < 16; o++) {
                const float* wp = ws + (tg*16 + o)*144 + ic*9;
                float w0 = wp[0], w1 = wp[1], w2 = wp[2];
                float w3 = wp[3], w4 = wp[4], w5 = wp[5];
                float w6 = wp[6], w7 = wp[7], w8 = wp[8];
#pragma unroll
                for (int dy = 0; dy < 2; dy++)
#pragma unroll
                    for (int dx = 0; dx < 2; dx++) {
                        acc[dy*2 + dx][o] +=
                              w0*in44[dy  ][dx] + w1*in44[dy  ][dx+1] + w2*in44[dy  ][dx+2]
                            + w3*in44[dy+1][dx] + w4*in44[dy+1][dx+1] + w5*in44[dy+1][dx+2]
                            + w6*in44[dy+2][dx] + w7*in44[dy+2][dx+1] + w8*in44[dy+2][dx+2];
                    }
            }
        }
    }
#pragma unroll
    for (int o = 0; o < 16; o++) {
        int oc = tg*16 + o;
        float bb = bias[oc];
#pragma unroll
        for (int dy = 0; dy < 2; dy++)
#pragma unroll
            for (int dx = 0; dx < 2; dx++) {
                float v = acc[dy*2 + dx][o] + bb;
                size_t idx = (size_t)(b*DD + oc)*HW + (ty0 + qy*2 + dy)*64 + tx0 + qx*2 + dx;
                __nv_bfloat16 h = __float2bfloat16(v);
                outH[idx] = h;
                outL[idx] = __float2bfloat16(v - __bfloat162float(h));
            }
    }
}

// ---------------------------------------------------------------------------
// Flash attention (FA2-style): Bq=128, warp owns 16 rows x 64 cols.
// P register-resident (S C-frags == PV A-frags). cp.async double buffering.
// SMEM elems: buf[2] x {KH,KL,VH,VL}[64x72] + QSH/QSL [64x136].
// ---------------------------------------------------------------------------
#define KVT   4608                       // 64*72 elems per sub-tile
#define BUFE  (4*KVT)                    // elems per buffer
#define QSE   (64*136)
#define ATTN_SMEM ((2*BUFE + 2*QSE) * 2)

__global__ __launch_bounds__(256) void k_attn_mma() {
    extern __shared__ char smraw[];
    __nv_bfloat16* smb = (__nv_bfloat16*)smraw;
    __nv_bfloat16* QSH = smb + 2*BUFE;
    __nv_bfloat16* QSL = QSH + QSE;

    int b  = blockIdx.y;
    int i0 = blockIdx.x * QTILE;
    int tid = threadIdx.x;
    int warp = tid >> 5, lane = tid & 31;
    int R0 = warp * 16;
    int g = lane >> 2, t = lane & 3;
    size_t base = (size_t)b*DD*NPIX;

    // ---- stage Q (hi/lo) [c][i], stride 136 ----
    {
        int c = tid >> 2, v0 = (tid & 3) * 4;   // 4 thr/row, 4 uint4 each (row=16 uint4)
        const uint4* gh = (const uint4*)&g_qH[base + (size_t)c*NPIX + i0];
        const uint4* gl = (const uint4*)&g_qL[base + (size_t)c*NPIX + i0];
        uint4* dh = (uint4*)&QSH[c*136];
        uint4* dl = (uint4*)&QSL[c*136];
#pragma unroll
        for (int r = 0; r < 4; r++) { dh[v0+r] = gh[v0+r]; dl[v0+r] = gl[v0+r]; }
    }
    __syncthreads();

    unsigned qaH[4][4], qaL[4][4];
    {
        int krow = (lane & 7) + ((lane >> 4) << 3);
        int mcol = R0 + ((lane >> 3) & 1) * 8;
#pragma unroll
        for (int ks = 0; ks < 4; ks++) {
            ldsm_x4_t(qaH[ks], &QSH[(ks*16 + krow)*136 + mcol]);
            ldsm_x4_t(qaL[ks], &QSL[(ks*16 + krow)*136 + mcol]);
        }
    }

    float m0 = -1e30f, m1 = -1e30f, l0 = 0.f, l1 = 0.f;
    float oAcc[8][4];
#pragma unroll
    for (int nb = 0; nb < 8; nb++)
#pragma unroll
        for (int q = 0; q < 4; q++) oAcc[nb][q] = 0.f;

    int kv_krow = (lane & 7) + (((lane >> 3) & 1) << 3);
    int kv_ncol = (lane >> 4) << 3;
    int v_nrow  = (lane & 7) + ((lane >> 4) << 3);
    int v_kcol  = ((lane >> 3) & 1) << 3;

    // tile-copy addressing: 4 thr/row, 2 uint4 per array per thread
    int cp_c = tid >> 2, cp_v = (tid & 3) * 2;
    size_t cp_row = base + (size_t)cp_c*NPIX;

    // prologue: prefetch tile 0 into buf 0
    {
        __nv_bfloat16* B = smb;
        size_t go = cp_row;
#pragma unroll
        for (int u = 0; u < 2; u++) {
            cp16((uint4*)&B[cp_c*72]          + cp_v+u, (const uint4*)&g_kH[go] + cp_v+u);
            cp16((uint4*)&B[KVT   + cp_c*72]  + cp_v+u, (const uint4*)&g_kL[go] + cp_v+u);
            cp16((uint4*)&B[2*KVT + cp_c*72]  + cp_v+u, (const uint4*)&g_vH[go] + cp_v+u);
            cp16((uint4*)&B[3*KVT + cp_c*72]  + cp_v+u, (const uint4*)&g_vL[go] + cp_v+u);
        }
        asm volatile("cp.async.commit_group;" ::: "memory");
    }

    for (int it = 0; it < 64; it++) {
        asm volatile("cp.async.wait_group 0;" ::: "memory");
        __syncthreads();
        // prefetch next tile into the other buffer (free: its consumers are 2 iters back)
        if (it + 1 < 64) {
            __nv_bfloat16* B = smb + ((it+1)&1)*BUFE;
            size_t go = cp_row + (it+1)*64;
#pragma unroll
            for (int u = 0; u < 2; u++) {
                cp16((uint4*)&B[cp_c*72]          + cp_v+u, (const uint4*)&g_kH[go] + cp_v+u);
                cp16((uint4*)&B[KVT   + cp_c*72]  + cp_v+u, (const uint4*)&g_kL[go] + cp_v+u);
                cp16((uint4*)&B[2*KVT + cp_c*72]  + cp_v+u, (const uint4*)&g_vH[go] + cp_v+u);
                cp16((uint4*)&B[3*KVT + cp_c*72]  + cp_v+u, (const uint4*)&g_vL[go] + cp_v+u);
            }
            asm volatile("cp.async.commit_group;" ::: "memory");
        }

        __nv_bfloat16* KH = smb + (it&1)*BUFE;
        __nv_bfloat16* KL = KH + KVT;
        __nv_bfloat16* VH = KH + 2*KVT;
        __nv_bfloat16* VL = KH + 3*KVT;

        // ---- S = Q^T K : p[nb][4], nb = 8 n-blocks of 8 ----
        float p[8][4];
#pragma unroll
        for (int nb = 0; nb < 8; nb++)
#pragma unroll
            for (int q = 0; q < 4; q++) p[nb][q] = 0.f;

#pragma unroll
        for (int ks = 0; ks < 4; ks++) {
#pragma unroll
            for (int nb2 = 0; nb2 < 4; nb2++) {
                unsigned bh[4], bl[4];
                ldsm_x4_t(bh, &KH[(ks*16 + kv_krow)*72 + nb2*16 + kv_ncol]);
                ldsm_x4_t(bl, &KL[(ks*16 + kv_krow)*72 + nb2*16 + kv_ncol]);
#pragma unroll
                for (int s = 0; s < 2; s++) {
                    mma_bf16(p[nb2*2+s], qaH[ks], &bh[s*2]);
                    mma_bf16(p[nb2*2+s], qaH[ks], &bl[s*2]);
                    mma_bf16(p[nb2*2+s], qaL[ks], &bh[s*2]);
                }
            }
        }

        // ---- warp-local online softmax (rows g, g+8; reduce over quad) ----
        float rm0 = -1e30f, rm1 = -1e30f;
#pragma unroll
        for (int nb = 0; nb < 8; nb++) {
            rm0 = fmaxf(rm0, fmaxf(p[nb][0], p[nb][1]));
            rm1 = fmaxf(rm1, fmaxf(p[nb][2], p[nb][3]));
        }
        rm0 = fmaxf(rm0, __shfl_xor_sync(0xffffffffu, rm0, 1));
        rm0 = fmaxf(rm0, __shfl_xor_sync(0xffffffffu, rm0, 2));
        rm1 = fmaxf(rm1, __shfl_xor_sync(0xffffffffu, rm1, 1));
        rm1 = fmaxf(rm1, __shfl_xor_sync(0xffffffffu, rm1, 2));
        float mn0 = fmaxf(m0, rm0), mn1 = fmaxf(m1, rm1);
        float sc0 = __expf(m0 - mn0), sc1 = __expf(m1 - mn1);
        m0 = mn0; m1 = mn1;

        float rs0 = 0.f, rs1 = 0.f;
#pragma unroll
        for (int nb = 0; nb < 8; nb++) {
            p[nb][0] = __expf(p[nb][0] - mn0);
            p[nb][1] = __expf(p[nb][1] - mn0);
            p[nb][2] = __expf(p[nb][2] - mn1);
            p[nb][3] = __expf(p[nb][3] - mn1);
            rs0 += p[nb][0] + p[nb][1];
            rs1 += p[nb][2] + p[nb][3];
        }
        rs0 += __shfl_xor_sync(0xffffffffu, rs0, 1);
        rs0 += __shfl_xor_sync(0xffffffffu, rs0, 2);
        rs1 += __shfl_xor_sync(0xffffffffu, rs1, 1);
        rs1 += __shfl_xor_sync(0xffffffffu, rs1, 2);
        l0 = l0*sc0 + rs0;
        l1 = l1*sc1 + rs1;
#pragma unroll
        for (int nb = 0; nb < 8; nb++) {
            oAcc[nb][0] *= sc0; oAcc[nb][1] *= sc0;
            oAcc[nb][2] *= sc1; oAcc[nb][3] *= sc1;
        }

        // ---- pack P into PV A-fragments (registers only) ----
        unsigned paH[4][4], paL[4][4];
#pragma unroll
        for (int kb = 0; kb < 4; kb++) {
            int n0 = 2*kb, n1 = 2*kb + 1;
            packhl(p[n0][0], p[n0][1], paH[kb][0], paL[kb][0]);
            packhl(p[n0][2], p[n0][3], paH[kb][1], paL[kb][1]);
            packhl(p[n1][0], p[n1][1], paH[kb][2], paL[kb][2]);
            packhl(p[n1][2], p[n1][3], paH[kb][3], paL[kb][3]);
        }

        // ---- O += P V ----
#pragma unroll
        for (int kb = 0; kb < 4; kb++) {
#pragma unroll
            for (int nb2 = 0; nb2 < 4; nb2++) {
                unsigned vh[4], vl[4];
                ldsm_x4(vh, &VH[(nb2*16 + v_nrow)*72 + kb*16 + v_kcol]);
                ldsm_x4(vl, &VL[(nb2*16 + v_nrow)*72 + kb*16 + v_kcol]);
#pragma unroll
                for (int s = 0; s < 2; s++) {
                    mma_bf16(oAcc[nb2*2+s], paH[kb], &vh[s*2]);
                    mma_bf16(oAcc[nb2*2+s], paH[kb], &vl[s*2]);
                    mma_bf16(oAcc[nb2*2+s], paL[kb], &vh[s*2]);
                }
            }
        }
    }

    // ---- epilogue: normalize, write g_ao [c][i] ----
    float inv0 = 1.f / l0, inv1 = 1.f / l1;
    int ia = i0 + R0 + g, ib = ia + 8;
#pragma unroll
    for (int nb = 0; nb < 8; nb++) {
        int c = nb*8 + 2*t;
        g_ao[(size_t)(b*DD + c  )*NPIX + ia] = oAcc[nb][0] * inv0;
        g_ao[(size_t)(b*DD + c+1)*NPIX + ia] = oAcc[nb][1] * inv0;
        g_ao[(size_t)(b*DD + c  )*NPIX + ib] = oAcc[nb][2] * inv1;
        g_ao[(size_t)(b*DD + c+1)*NPIX + ib] = oAcc[nb][3] * inv1;
    }
}

// ---------------------------------------------------------------------------
// out-projection + residual + LayerNorm (proven)
// ---------------------------------------------------------------------------
__global__ __launch_bounds__(256) void k_outproj_ln(const float* __restrict__ x,
                                                    const float* __restrict__ w,
                                                    const float* __restrict__ bias,
                                                    const float* __restrict__ gamma,
                                                    const float* __restrict__ lnw,
                                                    const float* __restrict__ lnb,
                                                    float* __restrict__ out) {
    int b  = blockIdx.y;
    int p0 = blockIdx.x * 64;
    int tid = threadIdx.x;
    int tp = tid & 63, tg = tid >> 6;
    __shared__ float xs[16][65];
    __shared__ float ws[256][17];
    __shared__ float red[2][4][64];

    float acc[64];
#pragma unroll
    for (int i = 0; i < 64; i++) acc[i] = 0.f;

    for (int d0 = 0; d0 < DD; d0 += 16) {
        __syncthreads();
#pragma unroll
        for (int r = 0; r < 4; r++) {
            int lin = tid + r * 256;
            int cc = lin >> 6, pp = lin & 63;
            xs[cc][pp] = g_ao[(size_t)(b*DD + d0 + cc)*HW + p0 + pp];
        }
#pragma unroll
        for (int r = 0; r < 16; r++) {
            int lin = tid + r * 256;
            int co = lin >> 4, cc = lin & 15;
            ws[co][cc] = w[co*DD + d0 + cc];
        }
        __syncthreads();
#pragma unroll 4
        for (int cc = 0; cc < 16; cc++) {
            float xv = xs[cc][tp];
#pragma unroll
            for (int oo = 0; oo < 64; oo++)
                acc[oo] += ws[tg*64 + oo][cc] * xv;
        }
    }

    float gg = gamma[0];
    float s = 0.f, ss = 0.f;
#pragma unroll
    for (int oo = 0; oo < 64; oo++) {
        int co = tg*64 + oo;
        float v = gg * x[(size_t)(b*CIN + co)*HW + p0 + tp] + acc[oo] + bias[co];
        acc[oo] = v;
        s += v; ss += v*v;
    }
    red[0][tg][tp] = s;
    red[1][tg][tp] = ss;
    __syncthreads();
    float st  = red[0][0][tp] + red[0][1][tp] + red[0][2][tp] + red[0][3][tp];
    float sst = red[1][0][tp] + red[1][1][tp] + red[1][2][tp] + red[1][3][tp];
    float mu  = st * (1.f/256.f);
    float var = sst * (1.f/256.f) - mu*mu;
    float rstd = rsqrtf(var + 1e-5f);
#pragma unroll
    for (int oo = 0; oo < 64; oo++) {
        int co = tg*64 + oo;
        out[(size_t)(b*CIN + co)*HW + p0 + tp] = (acc[oo] - mu) * rstd * lnw[co] + lnb[co];
    }
}

// ---------------------------------------------------------------------------
extern "C" void kernel_launch(void* const* d_in, const int* in_sizes, int n_in,
                              void* d_out, int out_size) {
    const float* x     = (const float*)d_in[0];
    const float* w_in  = (const float*)d_in[1];
    const float* b_in  = (const float*)d_in[2];
    const float* wq    = (const float*)d_in[3];
    const float* bq    = (const float*)d_in[4];
    const float* wk    = (const float*)d_in[5];
    const float* bk    = (const float*)d_in[6];
    const float* wv    = (const float*)d_in[7];
    const float* bv    = (const float*)d_in[8];
    const float* w_out = (const float*)d_in[9];
    const float* b_out = (const float*)d_in[10];
    const float* gamma = (const float*)d_in[11];
    const float* ln_w  = (const float*)d_in[12];
    const float* ln_b  = (const float*)d_in[13];
    float* out = (float*)d_out;

    cudaFuncSetAttribute(k_conv3x3,  cudaFuncAttributeMaxDynamicSharedMemorySize, CONV_SMEM);
    cudaFuncSetAttribute(k_attn_mma, cudaFuncAttributeMaxDynamicSharedMemorySize, ATTN_SMEM);

    k_inproj<<<dim3(64, BATCH), 256>>>(x, w_in, b_in);
    k_conv3x3<<<dim3(4, 4, BATCH*3), 256, CONV_SMEM>>>(wq, bq, wk, bk, wv, bv);
    k_attn_mma<<<dim3(NPIX/QTILE, BATCH), 256, ATTN_SMEM>>>();
    k_outproj_ln<<<dim3(64, BATCH), 256>>>(x, w_out, b_out, gamma, ln_w, ln_b, out);
}